// round 12
// baseline (speedup 1.0000x reference)
#include <cuda_runtime.h>
#include <cuda_bf16.h>
#include <cstdint>

// ---------------- fixed problem shapes ----------------
#define NN      50000
#define EE      800000
#define ELOOP   850000        // EE + NN self loops
#define GG      64
#define FIN     128
#define HIDD    64
#define HEADS   4
#define C1      256           // HEADS*HIDD
#define CLIN    32
#define MET     128
#define FUSED_IN 224          // HID + CLIN + MET
#define NB      196           // ceil(NN/256) scan blocks

// ---------------- device scratch (no allocs allowed) ----------------
__device__ uint32_t g_h1b [(size_t)NN * (C1/2)];  // bf16x2 packed h1 (agg gather)
__device__ float    g_out1[(size_t)NN * C1];      // layer1 output (post bias+relu)
__device__ uint32_t g_h2b [(size_t)NN * (HIDD/2)];// bf16x2 packed h2
__device__ float g_als1[NN * HEADS];
__device__ float g_ald1[NN * HEADS];
__device__ float g_als2[NN];
__device__ float g_ald2[NN];
__device__ float g_sums[GG * HIDD];
__device__ float g_cnt [GG];
__device__ float g_scal[8];     // [0]=sum(edge_attr), [1..4]=ce1[h], [5]=ce2
__device__ float g_part[512];   // per-block partial sums of edge_attr
// CSR by destination
__device__ int  g_row [NN + 1];
__device__ int  g_cur [NN];     // hist -> degree -> cursor
__device__ int  g_bsum[256];    // per-scan-block degree sums
__device__ int  g_boff[256];    // exclusive block offsets
__device__ int2 g_elist[ELOOP]; // (src, float_bits(edge_attr)) sorted by dst

__device__ __forceinline__ uint32_t pack_bf16(float a, float b) {
    __nv_bfloat162 h = __float22bfloat162_rn(make_float2(a, b));
    return *reinterpret_cast<uint32_t*>(&h);
}
__device__ __forceinline__ float2 unpack_bf16(uint32_t u) {
    return __bfloat1622float2(*reinterpret_cast<__nv_bfloat162*>(&u));
}

// ---------------- prep: zero scratch + partial sums of edge_attr ----------------
__global__ void prep_kernel(const float* __restrict__ ea) {
    __shared__ float sh[8];
    int i = blockIdx.x * blockDim.x + threadIdx.x;
    if (i < NN) { g_cur[i] = 0; g_als2[i] = 0.f; g_ald2[i] = 0.f; }
    if (i < GG * HIDD) g_sums[i] = 0.f;
    if (i < GG) g_cnt[i] = 0.f;
    if (i < 8)  g_scal[i] = 0.f;
    float s = 0.f;
    for (size_t e = i; e < EE; e += (size_t)512 * 256) s += ea[e];
    for (int o = 16; o; o >>= 1) s += __shfl_xor_sync(0xffffffffu, s, o);
    if ((threadIdx.x & 31) == 0) sh[threadIdx.x >> 5] = s;
    __syncthreads();
    if (threadIdx.x < 8) {
        float v = sh[threadIdx.x];
        for (int o = 4; o; o >>= 1) v += __shfl_xor_sync(0xffu, v, o);
        if (threadIdx.x == 0) g_part[blockIdx.x] = v;
    }
}

// ---------------- CSR build: histogram of dst ----------------
__global__ void hist_kernel(const int* __restrict__ ei) {
    int e = blockIdx.x * blockDim.x + threadIdx.x;
    if (e >= ELOOP) return;
    int d = (e < EE) ? ei[EE + e] : (e - EE);
    atomicAdd(&g_cur[d], 1);
}

// ---------------- scan stage 1: per-block degree sums ----------------
__global__ void scan1_kernel() {
    __shared__ int sh[8];
    int idx = blockIdx.x * 256 + threadIdx.x;
    int v = (idx < NN) ? g_cur[idx] : 0;
    int s = v;
    for (int o = 16; o; o >>= 1) s += __shfl_xor_sync(0xffffffffu, s, o);
    if ((threadIdx.x & 31) == 0) sh[threadIdx.x >> 5] = s;
    __syncthreads();
    if (threadIdx.x < 8) {
        int u = sh[threadIdx.x];
        for (int o = 4; o; o >>= 1) u += __shfl_xor_sync(0xffu, u, o);
        if (threadIdx.x == 0) g_bsum[blockIdx.x] = u;
    }
}

// ---- scan stage 2 (1 block x 256): block-offset scan + mean finalize + ce dots ----
__global__ void scan2_kernel(const float* __restrict__ We1, const float* __restrict__ ae1,
                             const float* __restrict__ We2, const float* __restrict__ ae2) {
    __shared__ int ss[256];
    __shared__ float fs[8];
    int t = threadIdx.x;
    float v = g_part[t] + g_part[t + 256];
    for (int o = 16; o; o >>= 1) v += __shfl_xor_sync(0xffffffffu, v, o);
    if ((t & 31) == 0) fs[t >> 5] = v;
    __syncthreads();
    if (t < 8) {
        float u = fs[t];
        for (int o = 4; o; o >>= 1) u += __shfl_xor_sync(0xffu, u, o);
        if (t == 0) g_scal[0] = u;
    }
    atomicAdd(&g_scal[1 + (t >> 6)], We1[t] * ae1[t]);
    if (t < 64) atomicAdd(&g_scal[5], We2[t] * ae2[t]);
    int b = (t < NB) ? g_bsum[t] : 0;
    ss[t] = b;
    __syncthreads();
    for (int off = 1; off < 256; off <<= 1) {
        int w = (t >= off) ? ss[t - off] : 0;
        __syncthreads();
        ss[t] += w;
        __syncthreads();
    }
    if (t < NB) g_boff[t] = ss[t] - b;
    if (t == 0) g_row[NN] = ELOOP;
}

// ---- scan stage 3: per-block exclusive scan + writeback ----
__global__ void scan3_kernel() {
    __shared__ int ss[256];
    int t = threadIdx.x;
    int idx = blockIdx.x * 256 + t;
    int d = (idx < NN) ? g_cur[idx] : 0;
    ss[t] = d;
    __syncthreads();
    for (int off = 1; off < 256; off <<= 1) {
        int w = (t >= off) ? ss[t - off] : 0;
        __syncthreads();
        ss[t] += w;
        __syncthreads();
    }
    int excl = ss[t] - d + g_boff[blockIdx.x];
    if (idx < NN) {
        g_row[idx] = excl;
        g_cur[idx] = excl;
    }
}

// ---------------- CSR build: scatter (src, edge_attr) ----------------
__global__ void scatter_kernel(const int* __restrict__ ei, const float* __restrict__ ea) {
    int e = blockIdx.x * blockDim.x + threadIdx.x;
    if (e >= ELOOP) return;
    int s, d; float att;
    if (e < EE) { s = ei[e]; d = ei[EE + e]; att = ea[e]; }
    else        { s = d = e - EE; att = g_scal[0] * (1.0f / EE); }
    int pos = atomicAdd(&g_cur[d], 1);
    g_elist[pos] = make_int2(s, __float_as_int(att));
}

// ---- TF32 GEMM, double-buffered, bf16 output + FUSED attention logits ----
template<int BN, int K, int LAYER>
__device__ __forceinline__ void gemm_tf32_body(const float* __restrict__ A,
                                               const float* __restrict__ B,
                                               uint32_t* __restrict__ Cb,
                                               const float* __restrict__ avS,
                                               const float* __restrict__ avD,
                                               int M, int Ncol) {
    constexpr int NF = BN / 16;
    __shared__ uint32_t As[2][128][20];
    __shared__ uint32_t Bs[2][16][BN + 8];
    int tid = threadIdx.x;
    int warp = tid >> 5, lane = tid & 31;
    int warp_m = warp & 3;
    int warp_n = warp >> 2;
    int m0 = blockIdx.y * 128, n0 = blockIdx.x * BN;
    int g = lane >> 2, t4 = lane & 3;

    int arow = tid >> 1, acb = (tid & 1) * 8;
    int brow = tid >> 4;
    int bcb  = (BN == 128) ? (tid & 15) * 8 : (tid & 15) * 4;

    float acc[2][NF][4];
#pragma unroll
    for (int mf = 0; mf < 2; mf++)
#pragma unroll
        for (int nf = 0; nf < NF; nf++)
#pragma unroll
            for (int i = 0; i < 4; i++) acc[mf][nf][i] = 0.f;

    float4 pa0, pa1, pb0, pb1;
    auto load_tile = [&](int k0) {
        pa0 = make_float4(0.f, 0.f, 0.f, 0.f);
        pa1 = make_float4(0.f, 0.f, 0.f, 0.f);
        if (m0 + arow < M) {
            const float* p = A + (size_t)(m0 + arow) * K + k0 + acb;
            pa0 = *(const float4*)p;
            pa1 = *(const float4*)(p + 4);
        }
        const float* q = B + (size_t)(k0 + brow) * Ncol + n0 + bcb;
        pb0 = *(const float4*)q;
        if (BN == 128) pb1 = *(const float4*)(q + 4);
    };
    auto store_tile = [&](int buf) {
        *(uint4*)&As[buf][arow][acb]     = *reinterpret_cast<uint4*>(&pa0);
        *(uint4*)&As[buf][arow][acb + 4] = *reinterpret_cast<uint4*>(&pa1);
        *(uint4*)&Bs[buf][brow][bcb]     = *reinterpret_cast<uint4*>(&pb0);
        if (BN == 128)
            *(uint4*)&Bs[buf][brow][bcb + 4] = *reinterpret_cast<uint4*>(&pb1);
    };
    auto compute = [&](int buf) {
#pragma unroll
        for (int ks = 0; ks < 16; ks += 8) {
            uint32_t a[2][4];
#pragma unroll
            for (int mf = 0; mf < 2; mf++) {
                int rb = warp_m * 32 + mf * 16;
                a[mf][0] = As[buf][rb + g][ks + t4];
                a[mf][1] = As[buf][rb + 8 + g][ks + t4];
                a[mf][2] = As[buf][rb + g][ks + 4 + t4];
                a[mf][3] = As[buf][rb + 8 + g][ks + 4 + t4];
            }
#pragma unroll
            for (int nf = 0; nf < NF; nf++) {
                int cb = warp_n * (BN / 2) + nf * 8;
                uint32_t b0 = Bs[buf][ks + t4][cb + g];
                uint32_t b1 = Bs[buf][ks + 4 + t4][cb + g];
#pragma unroll
                for (int mf = 0; mf < 2; mf++) {
                    asm volatile(
                        "mma.sync.aligned.m16n8k8.row.col.f32.tf32.tf32.f32 "
                        "{%0,%1,%2,%3}, {%4,%5,%6,%7}, {%8,%9}, {%0,%1,%2,%3};"
                        : "+f"(acc[mf][nf][0]), "+f"(acc[mf][nf][1]),
                          "+f"(acc[mf][nf][2]), "+f"(acc[mf][nf][3])
                        : "r"(a[mf][0]), "r"(a[mf][1]), "r"(a[mf][2]), "r"(a[mf][3]),
                          "r"(b0), "r"(b1));
                }
            }
        }
    };

    load_tile(0);
    store_tile(0);
    __syncthreads();
    int cur = 0;
    for (int k0 = 0; k0 < K; k0 += 16) {
        bool more = (k0 + 16 < K);
        if (more) load_tile(k0 + 16);
        compute(cur);
        if (more) store_tile(cur ^ 1);
        __syncthreads();
        cur ^= 1;
    }

    // ---- bf16 store ----
#pragma unroll
    for (int mf = 0; mf < 2; mf++) {
#pragma unroll
        for (int nf = 0; nf < NF; nf++) {
            int row0 = m0 + warp_m * 32 + mf * 16 + g;
            int col  = n0 + warp_n * (BN / 2) + nf * 8 + 2 * t4;
            if (row0 < M)
                Cb[(size_t)row0 * (Ncol / 2) + col / 2] = pack_bf16(acc[mf][nf][0], acc[mf][nf][1]);
            if (row0 + 8 < M)
                Cb[(size_t)(row0 + 8) * (Ncol / 2) + col / 2] = pack_bf16(acc[mf][nf][2], acc[mf][nf][3]);
        }
    }

    // ---- fused attention logits ----
    float2 wS[NF], wD[NF];
    int cbase = (LAYER == 1) ? ((blockIdx.x * 2 + warp_n) * 64) : (warp_n * (BN / 2));
#pragma unroll
    for (int nf = 0; nf < NF; nf++) {
        int c = cbase + nf * 8 + 2 * t4;
        wS[nf] = *(const float2*)(avS + c);
        wD[nf] = *(const float2*)(avD + c);
    }
#pragma unroll
    for (int mf = 0; mf < 2; mf++) {
        float ss0 = 0.f, dd0 = 0.f, ss1 = 0.f, dd1 = 0.f;
#pragma unroll
        for (int nf = 0; nf < NF; nf++) {
            ss0 += acc[mf][nf][0] * wS[nf].x + acc[mf][nf][1] * wS[nf].y;
            dd0 += acc[mf][nf][0] * wD[nf].x + acc[mf][nf][1] * wD[nf].y;
            ss1 += acc[mf][nf][2] * wS[nf].x + acc[mf][nf][3] * wS[nf].y;
            dd1 += acc[mf][nf][2] * wD[nf].x + acc[mf][nf][3] * wD[nf].y;
        }
        ss0 += __shfl_xor_sync(0xffffffffu, ss0, 1); ss0 += __shfl_xor_sync(0xffffffffu, ss0, 2);
        dd0 += __shfl_xor_sync(0xffffffffu, dd0, 1); dd0 += __shfl_xor_sync(0xffffffffu, dd0, 2);
        ss1 += __shfl_xor_sync(0xffffffffu, ss1, 1); ss1 += __shfl_xor_sync(0xffffffffu, ss1, 2);
        dd1 += __shfl_xor_sync(0xffffffffu, dd1, 1); dd1 += __shfl_xor_sync(0xffffffffu, dd1, 2);
        if (t4 == 0) {
            int row0 = m0 + warp_m * 32 + mf * 16 + g;
            if (LAYER == 1) {
                int head = blockIdx.x * 2 + warp_n;
                if (row0 < M)     { g_als1[row0 * 4 + head] = ss0; g_ald1[row0 * 4 + head] = dd0; }
                if (row0 + 8 < M) { g_als1[(row0 + 8) * 4 + head] = ss1; g_ald1[(row0 + 8) * 4 + head] = dd1; }
            } else {
                if (row0 < M)     { atomicAdd(&g_als2[row0], ss0); atomicAdd(&g_ald2[row0], dd0); }
                if (row0 + 8 < M) { atomicAdd(&g_als2[row0 + 8], ss1); atomicAdd(&g_ald2[row0 + 8], dd1); }
            }
        }
    }
}

__global__ void __launch_bounds__(256, 2)
gemm1_kernel(const float* __restrict__ x, const float* __restrict__ W1,
             const float* __restrict__ as1, const float* __restrict__ ad1) {
    gemm_tf32_body<128, FIN, 1>(x, W1, g_h1b, as1, ad1, NN, C1);
}
__global__ void __launch_bounds__(256, 2)
gemm2_kernel(const float* __restrict__ W2,
             const float* __restrict__ as2, const float* __restrict__ ad2) {
    gemm_tf32_body<64, C1, 2>(g_out1, W2, g_h2b, as2, ad2, NN, HIDD);
}

// ---- layer-1 aggregation: TWO warps per dst node (edge-list split) ----
// NOTE: den is PER-HEAD (lane-dependent) -> per-lane smem combine.
__global__ void agg1_kernel(const float* __restrict__ b1) {
    __shared__ float s_acc[4][32][8];
    __shared__ float s_den[4][32];
    int warp = threadIdx.x >> 5;
    int lane = threadIdx.x & 31;
    int pair = warp >> 1;          // node within block
    int half = warp & 1;
    int n = blockIdx.x * 4 + pair;
    int beg = g_row[n], end = g_row[n + 1];
    int cnt = end - beg;
    int c0 = (cnt + 1) >> 1;
    int jb = half ? (beg + c0) : beg;
    int je = half ? end : (beg + c0);

    int h = lane >> 3;
    float ald = g_ald1[n * 4 + h];
    float ce  = g_scal[1 + h];
    float4 acc0 = make_float4(0.f, 0.f, 0.f, 0.f);
    float4 acc1 = make_float4(0.f, 0.f, 0.f, 0.f);
    float den = 0.f;
    int j = jb;
    for (; j + 4 <= je; j += 4) {
        int2 se[4];
#pragma unroll
        for (int q = 0; q < 4; q++) se[q] = __ldcs(&g_elist[j + q]);
        uint4 p[4]; float al[4];
#pragma unroll
        for (int q = 0; q < 4; q++) {
            p[q]  = ((const uint4*)(g_h1b + (size_t)se[q].x * (C1 / 2)))[lane];
            al[q] = g_als1[se[q].x * 4 + h];
        }
        float ex[4];
#pragma unroll
        for (int q = 0; q < 4; q++) {
            float z = al[q] + ald + __int_as_float(se[q].y) * ce;
            z = z > 0.f ? z : 0.2f * z;
            ex[q] = __expf(z);
        }
#pragma unroll
        for (int q = 0; q < 4; q++) {
            float2 f0 = unpack_bf16(p[q].x), f1 = unpack_bf16(p[q].y);
            float2 f2 = unpack_bf16(p[q].z), f3 = unpack_bf16(p[q].w);
            den += ex[q];
            acc0.x += ex[q] * f0.x; acc0.y += ex[q] * f0.y;
            acc0.z += ex[q] * f1.x; acc0.w += ex[q] * f1.y;
            acc1.x += ex[q] * f2.x; acc1.y += ex[q] * f2.y;
            acc1.z += ex[q] * f3.x; acc1.w += ex[q] * f3.y;
        }
    }
    for (; j < je; j++) {
        int2 se = __ldcs(&g_elist[j]);
        uint4 p = ((const uint4*)(g_h1b + (size_t)se.x * (C1 / 2)))[lane];
        float z = g_als1[se.x * 4 + h] + ald + __int_as_float(se.y) * ce;
        z = z > 0.f ? z : 0.2f * z;
        float ex = __expf(z);
        float2 f0 = unpack_bf16(p.x), f1 = unpack_bf16(p.y);
        float2 f2 = unpack_bf16(p.z), f3 = unpack_bf16(p.w);
        den += ex;
        acc0.x += ex * f0.x; acc0.y += ex * f0.y;
        acc0.z += ex * f1.x; acc0.w += ex * f1.y;
        acc1.x += ex * f2.x; acc1.y += ex * f2.y;
        acc1.z += ex * f3.x; acc1.w += ex * f3.y;
    }
    // pair reduction via smem (per-lane den!)
    if (half == 1) {
        *(float4*)&s_acc[pair][lane][0] = acc0;
        *(float4*)&s_acc[pair][lane][4] = acc1;
        s_den[pair][lane] = den;
    }
    __syncthreads();
    if (half == 0) {
        float4 q0 = *(float4*)&s_acc[pair][lane][0];
        float4 q1 = *(float4*)&s_acc[pair][lane][4];
        acc0.x += q0.x; acc0.y += q0.y; acc0.z += q0.z; acc0.w += q0.w;
        acc1.x += q1.x; acc1.y += q1.y; acc1.z += q1.z; acc1.w += q1.w;
        den += s_den[pair][lane];
        float inv = 1.f / (den + 1e-16f);
        const float4* bp = (const float4*)b1;
        float4 bb0 = bp[lane * 2], bb1 = bp[lane * 2 + 1];
        float4 o0, o1;
        o0.x = fmaxf(acc0.x * inv + bb0.x, 0.f);
        o0.y = fmaxf(acc0.y * inv + bb0.y, 0.f);
        o0.z = fmaxf(acc0.z * inv + bb0.z, 0.f);
        o0.w = fmaxf(acc0.w * inv + bb0.w, 0.f);
        o1.x = fmaxf(acc1.x * inv + bb1.x, 0.f);
        o1.y = fmaxf(acc1.y * inv + bb1.y, 0.f);
        o1.z = fmaxf(acc1.z * inv + bb1.z, 0.f);
        o1.w = fmaxf(acc1.w * inv + bb1.w, 0.f);
        float4* op = (float4*)(g_out1 + (size_t)n * C1);
        op[lane * 2] = o0;
        op[lane * 2 + 1] = o1;
    }
}

// ---- layer-2 aggregation: TWO warps per node + bias + LayerNorm + pool ----
// (single head: den is lane-invariant, scalar combine is correct)
__global__ void agg2_ln_pool_kernel(const float* __restrict__ b2,
                                    const float* __restrict__ lng,
                                    const float* __restrict__ lnb,
                                    const int* __restrict__ batch) {
    __shared__ float s_acc[4][32][2];
    __shared__ float s_den[4];
    int warp = threadIdx.x >> 5;
    int lane = threadIdx.x & 31;
    int pair = warp >> 1;
    int half = warp & 1;
    int n = blockIdx.x * 4 + pair;
    int beg = g_row[n], end = g_row[n + 1];
    int cnt = end - beg;
    int c0 = (cnt + 1) >> 1;
    int jb = half ? (beg + c0) : beg;
    int je = half ? end : (beg + c0);

    float ald = g_ald2[n];
    float ce  = g_scal[5];
    float2 acc = make_float2(0.f, 0.f);
    float den = 0.f;
    int j = jb;
    for (; j + 4 <= je; j += 4) {
        int2 se[4];
#pragma unroll
        for (int q = 0; q < 4; q++) se[q] = __ldcs(&g_elist[j + q]);
        uint32_t p[4]; float al[4];
#pragma unroll
        for (int q = 0; q < 4; q++) {
            p[q]  = (g_h2b + (size_t)se[q].x * (HIDD / 2))[lane];
            al[q] = g_als2[se[q].x];
        }
        float ex[4];
#pragma unroll
        for (int q = 0; q < 4; q++) {
            float z = al[q] + ald + __int_as_float(se[q].y) * ce;
            z = z > 0.f ? z : 0.2f * z;
            ex[q] = __expf(z);
        }
#pragma unroll
        for (int q = 0; q < 4; q++) {
            float2 f = unpack_bf16(p[q]);
            den += ex[q];
            acc.x += ex[q] * f.x;
            acc.y += ex[q] * f.y;
        }
    }
    for (; j < je; j++) {
        int2 se = __ldcs(&g_elist[j]);
        uint32_t p = (g_h2b + (size_t)se.x * (HIDD / 2))[lane];
        float z = g_als2[se.x] + ald + __int_as_float(se.y) * ce;
        z = z > 0.f ? z : 0.2f * z;
        float ex = __expf(z);
        float2 f = unpack_bf16(p);
        den += ex;
        acc.x += ex * f.x;
        acc.y += ex * f.y;
    }
    if (half == 1) {
        s_acc[pair][lane][0] = acc.x;
        s_acc[pair][lane][1] = acc.y;
        if (lane == 0) s_den[pair] = den;
    }
    __syncthreads();
    if (half == 0) {
        acc.x += s_acc[pair][lane][0];
        acc.y += s_acc[pair][lane][1];
        den += s_den[pair];
        float inv = 1.f / (den + 1e-16f);
        float2 bb = ((const float2*)b2)[lane];
        float vx = acc.x * inv + bb.x;
        float vy = acc.y * inv + bb.y;
        float s = vx + vy;
        for (int o = 16; o; o >>= 1) s += __shfl_xor_sync(0xffffffffu, s, o);
        float mu = s * (1.0f / 64.0f);
        float dx = vx - mu, dy = vy - mu;
        float q = dx * dx + dy * dy;
        for (int o = 16; o; o >>= 1) q += __shfl_xor_sync(0xffffffffu, q, o);
        float r = rsqrtf(q * (1.0f / 64.0f) + 1e-5f);
        float y0 = dx * r * lng[lane * 2]     + lnb[lane * 2];
        float y1 = dy * r * lng[lane * 2 + 1] + lnb[lane * 2 + 1];
        int g = batch[n];
        atomicAdd(&g_sums[g * 64 + lane * 2],     y0);
        atomicAdd(&g_sums[g * 64 + lane * 2 + 1], y1);
        if (lane == 0) atomicAdd(&g_cnt[g], 1.0f);
    }
}

// ---------------- per-graph MLP head (block per graph, 64 threads) ----------------
__global__ void mlp_kernel(const float* __restrict__ clin, const float* __restrict__ met,
                           const float* __restrict__ Wf1, const float* __restrict__ bf1,
                           const float* __restrict__ Wf2, const float* __restrict__ bf2,
                           const float* __restrict__ Wr,  const float* __restrict__ br,
                           float* __restrict__ out) {
    int g = blockIdx.x, t = threadIdx.x;   // 64 threads
    __shared__ float fused[FUSED_IN];
    __shared__ float l1[64];
    __shared__ float l2[32];
    float cnt = g_cnt[g]; cnt = cnt > 1.f ? cnt : 1.f;
    float e = g_sums[g * 64 + t] / cnt;
    fused[t] = e;
    out[GG + g * 64 + t] = e;              // graph_embedding at offset 64
    if (t < 32) fused[64 + t] = clin[g * 32 + t];
    fused[96 + t]  = met[g * 128 + t];
    fused[160 + t] = met[g * 128 + 64 + t];
    __syncthreads();
    float acc = bf1[t];
#pragma unroll 8
    for (int k = 0; k < FUSED_IN; k++) acc += fused[k] * Wf1[k * 64 + t];
    l1[t] = acc > 0.f ? acc : 0.f;
    __syncthreads();
    if (t < 32) {
        float a2 = bf2[t];
#pragma unroll 8
        for (int j = 0; j < 64; j++) a2 += l1[j] * Wf2[j * 32 + t];
        a2 = a2 > 0.f ? a2 : 0.f;
        l2[t] = a2;
        out[GG + GG * 64 + g * 32 + t] = a2;   // latent at offset 64 + 4096
    }
    __syncthreads();
    if (t == 0) {
        float r = br[0];
#pragma unroll
        for (int j = 0; j < 32; j++) r += l2[j] * Wr[j];
        out[g] = r;                        // risk at offset 0
    }
}

// ---------------- launch ----------------
extern "C" void kernel_launch(void* const* d_in, const int* in_sizes, int n_in,
                              void* d_out, int out_size) {
    const float* x    = (const float*)d_in[0];
    const int*   ei   = (const int*)d_in[1];
    const float* ea   = (const float*)d_in[2];
    const int*   bat  = (const int*)d_in[3];
    const float* clin = (const float*)d_in[4];
    const float* met  = (const float*)d_in[5];
    const float* W1   = (const float*)d_in[6];
    const float* as1  = (const float*)d_in[7];
    const float* ad1  = (const float*)d_in[8];
    const float* ae1  = (const float*)d_in[9];
    const float* We1  = (const float*)d_in[10];
    const float* b1   = (const float*)d_in[11];
    const float* W2   = (const float*)d_in[12];
    const float* as2  = (const float*)d_in[13];
    const float* ad2  = (const float*)d_in[14];
    const float* ae2  = (const float*)d_in[15];
    const float* We2  = (const float*)d_in[16];
    const float* b2   = (const float*)d_in[17];
    const float* lng  = (const float*)d_in[18];
    const float* lnb  = (const float*)d_in[19];
    const float* Wf1  = (const float*)d_in[20];
    const float* bf1  = (const float*)d_in[21];
    const float* Wf2  = (const float*)d_in[22];
    const float* bf2  = (const float*)d_in[23];
    const float* Wr   = (const float*)d_in[24];
    const float* br   = (const float*)d_in[25];
    float* out = (float*)d_out;

    // fork: CSR chain on side stream, GEMM(+logits) on main stream
    cudaStream_t s2;
    cudaEvent_t e0, e1;
    cudaStreamCreateWithFlags(&s2, cudaStreamNonBlocking);
    cudaEventCreateWithFlags(&e0, cudaEventDisableTiming);
    cudaEventCreateWithFlags(&e1, cudaEventDisableTiming);

    cudaEventRecord(e0, 0);
    cudaStreamWaitEvent(s2, e0, 0);

    prep_kernel<<<512, 256, 0, s2>>>(ea);                        // 0
    hist_kernel<<<(ELOOP + 255) / 256, 256, 0, s2>>>(ei);        // 1
    scan1_kernel<<<NB, 256, 0, s2>>>();                          // 2
    gemm1_kernel<<<dim3(C1 / 128, (NN + 127) / 128), 256>>>(x, W1, as1, ad1); // 3 (profiled)
    scan2_kernel<<<1, 256, 0, s2>>>(We1, ae1, We2, ae2);         // 4
    scan3_kernel<<<NB, 256, 0, s2>>>();                          // 5
    scatter_kernel<<<(ELOOP + 255) / 256, 256, 0, s2>>>(ei, ea); // 6
    cudaEventRecord(e1, s2);
    cudaStreamWaitEvent(0, e1, 0);

    // layer 1 aggregation (needs CSR + gemm1 logits): 2 warps/node, 4 nodes/block
    agg1_kernel<<<NN / 4, 256>>>(b1);

    // layer 2 (gemm2 fuses logits2; g_als2/g_ald2 zeroed by prep)
    gemm2_kernel<<<dim3(1, (NN + 127) / 128), 256>>>(W2, as2, ad2);
    agg2_ln_pool_kernel<<<NN / 4, 256>>>(b2, lng, lnb, bat);

    // head
    mlp_kernel<<<GG, 64>>>(clin, met, Wf1, bf1, Wf2, bf2, Wr, br, out);
    // streams/events intentionally not destroyed (graph may reference them)
}

// round 13
// speedup vs baseline: 1.0846x; 1.0846x over previous
#include <cuda_runtime.h>
#include <cuda_bf16.h>
#include <cstdint>

// ---------------- fixed problem shapes ----------------
#define NN      50000
#define EE      800000
#define ELOOP   850000        // EE + NN self loops
#define GG      64
#define FIN     128
#define HIDD    64
#define HEADS   4
#define C1      256           // HEADS*HIDD
#define CLIN    32
#define MET     128
#define FUSED_IN 224          // HID + CLIN + MET
#define NB      196           // ceil(NN/256) scan blocks

// ---------------- device scratch (no allocs allowed) ----------------
__device__ uint32_t g_h1b [(size_t)NN * (C1/2)];  // bf16x2 packed h1 (agg gather)
__device__ float    g_out1[(size_t)NN * C1];      // layer1 output (post bias+relu)
__device__ uint32_t g_h2b [(size_t)NN * (HIDD/2)];// bf16x2 packed h2
__device__ float g_als1[NN * HEADS];
__device__ float g_ald1[NN * HEADS];
__device__ float g_als2[NN];
__device__ float g_ald2[NN];
__device__ float g_sums[GG * HIDD];
__device__ float g_cnt [GG];
__device__ float g_scal[8];     // [0]=sum(edge_attr), [1..4]=ce1[h], [5]=ce2
__device__ float g_part[512];   // per-block partial sums of edge_attr
// CSR by destination
__device__ int  g_row [NN + 1];
__device__ int  g_cur [NN];     // hist -> degree -> cursor
__device__ int  g_bsum[256];    // per-scan-block degree sums
__device__ int  g_boff[256];    // exclusive block offsets
__device__ int2 g_elist[ELOOP]; // (src, float_bits(edge_attr)) sorted by dst

__device__ __forceinline__ uint32_t pack_bf16(float a, float b) {
    __nv_bfloat162 h = __float22bfloat162_rn(make_float2(a, b));
    return *reinterpret_cast<uint32_t*>(&h);
}
__device__ __forceinline__ float2 unpack_bf16(uint32_t u) {
    return __bfloat1622float2(*reinterpret_cast<__nv_bfloat162*>(&u));
}

// ---------------- prep: zero scratch + partial sums of edge_attr ----------------
__global__ void prep_kernel(const float* __restrict__ ea) {
    __shared__ float sh[8];
    int i = blockIdx.x * blockDim.x + threadIdx.x;
    if (i < NN) { g_cur[i] = 0; g_als2[i] = 0.f; g_ald2[i] = 0.f; }
    if (i < GG * HIDD) g_sums[i] = 0.f;
    if (i < GG) g_cnt[i] = 0.f;
    if (i < 8)  g_scal[i] = 0.f;
    float s = 0.f;
    for (size_t e = i; e < EE; e += (size_t)512 * 256) s += ea[e];
    for (int o = 16; o; o >>= 1) s += __shfl_xor_sync(0xffffffffu, s, o);
    if ((threadIdx.x & 31) == 0) sh[threadIdx.x >> 5] = s;
    __syncthreads();
    if (threadIdx.x < 8) {
        float v = sh[threadIdx.x];
        for (int o = 4; o; o >>= 1) v += __shfl_xor_sync(0xffu, v, o);
        if (threadIdx.x == 0) g_part[blockIdx.x] = v;
    }
}

// ---------------- CSR build: histogram of dst ----------------
__global__ void hist_kernel(const int* __restrict__ ei) {
    int e = blockIdx.x * blockDim.x + threadIdx.x;
    if (e >= ELOOP) return;
    int d = (e < EE) ? ei[EE + e] : (e - EE);
    atomicAdd(&g_cur[d], 1);
}

// ---------------- scan stage 1: per-block degree sums ----------------
__global__ void scan1_kernel() {
    __shared__ int sh[8];
    int idx = blockIdx.x * 256 + threadIdx.x;
    int v = (idx < NN) ? g_cur[idx] : 0;
    int s = v;
    for (int o = 16; o; o >>= 1) s += __shfl_xor_sync(0xffffffffu, s, o);
    if ((threadIdx.x & 31) == 0) sh[threadIdx.x >> 5] = s;
    __syncthreads();
    if (threadIdx.x < 8) {
        int u = sh[threadIdx.x];
        for (int o = 4; o; o >>= 1) u += __shfl_xor_sync(0xffu, u, o);
        if (threadIdx.x == 0) g_bsum[blockIdx.x] = u;
    }
}

// ---- scan stage 2 (1 block x 256): block-offset scan + mean finalize + ce dots ----
__global__ void scan2_kernel(const float* __restrict__ We1, const float* __restrict__ ae1,
                             const float* __restrict__ We2, const float* __restrict__ ae2) {
    __shared__ int ss[256];
    __shared__ float fs[8];
    int t = threadIdx.x;
    float v = g_part[t] + g_part[t + 256];
    for (int o = 16; o; o >>= 1) v += __shfl_xor_sync(0xffffffffu, v, o);
    if ((t & 31) == 0) fs[t >> 5] = v;
    __syncthreads();
    if (t < 8) {
        float u = fs[t];
        for (int o = 4; o; o >>= 1) u += __shfl_xor_sync(0xffu, u, o);
        if (t == 0) g_scal[0] = u;
    }
    atomicAdd(&g_scal[1 + (t >> 6)], We1[t] * ae1[t]);
    if (t < 64) atomicAdd(&g_scal[5], We2[t] * ae2[t]);
    int b = (t < NB) ? g_bsum[t] : 0;
    ss[t] = b;
    __syncthreads();
    for (int off = 1; off < 256; off <<= 1) {
        int w = (t >= off) ? ss[t - off] : 0;
        __syncthreads();
        ss[t] += w;
        __syncthreads();
    }
    if (t < NB) g_boff[t] = ss[t] - b;
    if (t == 0) g_row[NN] = ELOOP;
}

// ---- scan stage 3: per-block exclusive scan + writeback ----
__global__ void scan3_kernel() {
    __shared__ int ss[256];
    int t = threadIdx.x;
    int idx = blockIdx.x * 256 + t;
    int d = (idx < NN) ? g_cur[idx] : 0;
    ss[t] = d;
    __syncthreads();
    for (int off = 1; off < 256; off <<= 1) {
        int w = (t >= off) ? ss[t - off] : 0;
        __syncthreads();
        ss[t] += w;
        __syncthreads();
    }
    int excl = ss[t] - d + g_boff[blockIdx.x];
    if (idx < NN) {
        g_row[idx] = excl;
        g_cur[idx] = excl;
    }
}

// ---------------- CSR build: scatter (src, edge_attr) ----------------
__global__ void scatter_kernel(const int* __restrict__ ei, const float* __restrict__ ea) {
    int e = blockIdx.x * blockDim.x + threadIdx.x;
    if (e >= ELOOP) return;
    int s, d; float att;
    if (e < EE) { s = ei[e]; d = ei[EE + e]; att = ea[e]; }
    else        { s = d = e - EE; att = g_scal[0] * (1.0f / EE); }
    int pos = atomicAdd(&g_cur[d], 1);
    g_elist[pos] = make_int2(s, __float_as_int(att));
}

// ---- TF32 GEMM, double-buffered, bf16 output + FUSED attention logits ----
template<int BN, int K, int LAYER>
__device__ __forceinline__ void gemm_tf32_body(const float* __restrict__ A,
                                               const float* __restrict__ B,
                                               uint32_t* __restrict__ Cb,
                                               const float* __restrict__ avS,
                                               const float* __restrict__ avD,
                                               int M, int Ncol) {
    constexpr int NF = BN / 16;
    __shared__ uint32_t As[2][128][20];
    __shared__ uint32_t Bs[2][16][BN + 8];
    int tid = threadIdx.x;
    int warp = tid >> 5, lane = tid & 31;
    int warp_m = warp & 3;
    int warp_n = warp >> 2;
    int m0 = blockIdx.y * 128, n0 = blockIdx.x * BN;
    int g = lane >> 2, t4 = lane & 3;

    int arow = tid >> 1, acb = (tid & 1) * 8;
    int brow = tid >> 4;
    int bcb  = (BN == 128) ? (tid & 15) * 8 : (tid & 15) * 4;

    float acc[2][NF][4];
#pragma unroll
    for (int mf = 0; mf < 2; mf++)
#pragma unroll
        for (int nf = 0; nf < NF; nf++)
#pragma unroll
            for (int i = 0; i < 4; i++) acc[mf][nf][i] = 0.f;

    float4 pa0, pa1, pb0, pb1;
    auto load_tile = [&](int k0) {
        pa0 = make_float4(0.f, 0.f, 0.f, 0.f);
        pa1 = make_float4(0.f, 0.f, 0.f, 0.f);
        if (m0 + arow < M) {
            const float* p = A + (size_t)(m0 + arow) * K + k0 + acb;
            pa0 = *(const float4*)p;
            pa1 = *(const float4*)(p + 4);
        }
        const float* q = B + (size_t)(k0 + brow) * Ncol + n0 + bcb;
        pb0 = *(const float4*)q;
        if (BN == 128) pb1 = *(const float4*)(q + 4);
    };
    auto store_tile = [&](int buf) {
        *(uint4*)&As[buf][arow][acb]     = *reinterpret_cast<uint4*>(&pa0);
        *(uint4*)&As[buf][arow][acb + 4] = *reinterpret_cast<uint4*>(&pa1);
        *(uint4*)&Bs[buf][brow][bcb]     = *reinterpret_cast<uint4*>(&pb0);
        if (BN == 128)
            *(uint4*)&Bs[buf][brow][bcb + 4] = *reinterpret_cast<uint4*>(&pb1);
    };
    auto compute = [&](int buf) {
#pragma unroll
        for (int ks = 0; ks < 16; ks += 8) {
            uint32_t a[2][4];
#pragma unroll
            for (int mf = 0; mf < 2; mf++) {
                int rb = warp_m * 32 + mf * 16;
                a[mf][0] = As[buf][rb + g][ks + t4];
                a[mf][1] = As[buf][rb + 8 + g][ks + t4];
                a[mf][2] = As[buf][rb + g][ks + 4 + t4];
                a[mf][3] = As[buf][rb + 8 + g][ks + 4 + t4];
            }
#pragma unroll
            for (int nf = 0; nf < NF; nf++) {
                int cb = warp_n * (BN / 2) + nf * 8;
                uint32_t b0 = Bs[buf][ks + t4][cb + g];
                uint32_t b1 = Bs[buf][ks + 4 + t4][cb + g];
#pragma unroll
                for (int mf = 0; mf < 2; mf++) {
                    asm volatile(
                        "mma.sync.aligned.m16n8k8.row.col.f32.tf32.tf32.f32 "
                        "{%0,%1,%2,%3}, {%4,%5,%6,%7}, {%8,%9}, {%0,%1,%2,%3};"
                        : "+f"(acc[mf][nf][0]), "+f"(acc[mf][nf][1]),
                          "+f"(acc[mf][nf][2]), "+f"(acc[mf][nf][3])
                        : "r"(a[mf][0]), "r"(a[mf][1]), "r"(a[mf][2]), "r"(a[mf][3]),
                          "r"(b0), "r"(b1));
                }
            }
        }
    };

    load_tile(0);
    store_tile(0);
    __syncthreads();
    int cur = 0;
    for (int k0 = 0; k0 < K; k0 += 16) {
        bool more = (k0 + 16 < K);
        if (more) load_tile(k0 + 16);
        compute(cur);
        if (more) store_tile(cur ^ 1);
        __syncthreads();
        cur ^= 1;
    }

    // ---- bf16 store ----
#pragma unroll
    for (int mf = 0; mf < 2; mf++) {
#pragma unroll
        for (int nf = 0; nf < NF; nf++) {
            int row0 = m0 + warp_m * 32 + mf * 16 + g;
            int col  = n0 + warp_n * (BN / 2) + nf * 8 + 2 * t4;
            if (row0 < M)
                Cb[(size_t)row0 * (Ncol / 2) + col / 2] = pack_bf16(acc[mf][nf][0], acc[mf][nf][1]);
            if (row0 + 8 < M)
                Cb[(size_t)(row0 + 8) * (Ncol / 2) + col / 2] = pack_bf16(acc[mf][nf][2], acc[mf][nf][3]);
        }
    }

    // ---- fused attention logits ----
    float2 wS[NF], wD[NF];
    int cbase = (LAYER == 1) ? ((blockIdx.x * 2 + warp_n) * 64) : (warp_n * (BN / 2));
#pragma unroll
    for (int nf = 0; nf < NF; nf++) {
        int c = cbase + nf * 8 + 2 * t4;
        wS[nf] = *(const float2*)(avS + c);
        wD[nf] = *(const float2*)(avD + c);
    }
#pragma unroll
    for (int mf = 0; mf < 2; mf++) {
        float ss0 = 0.f, dd0 = 0.f, ss1 = 0.f, dd1 = 0.f;
#pragma unroll
        for (int nf = 0; nf < NF; nf++) {
            ss0 += acc[mf][nf][0] * wS[nf].x + acc[mf][nf][1] * wS[nf].y;
            dd0 += acc[mf][nf][0] * wD[nf].x + acc[mf][nf][1] * wD[nf].y;
            ss1 += acc[mf][nf][2] * wS[nf].x + acc[mf][nf][3] * wS[nf].y;
            dd1 += acc[mf][nf][2] * wD[nf].x + acc[mf][nf][3] * wD[nf].y;
        }
        ss0 += __shfl_xor_sync(0xffffffffu, ss0, 1); ss0 += __shfl_xor_sync(0xffffffffu, ss0, 2);
        dd0 += __shfl_xor_sync(0xffffffffu, dd0, 1); dd0 += __shfl_xor_sync(0xffffffffu, dd0, 2);
        ss1 += __shfl_xor_sync(0xffffffffu, ss1, 1); ss1 += __shfl_xor_sync(0xffffffffu, ss1, 2);
        dd1 += __shfl_xor_sync(0xffffffffu, dd1, 1); dd1 += __shfl_xor_sync(0xffffffffu, dd1, 2);
        if (t4 == 0) {
            int row0 = m0 + warp_m * 32 + mf * 16 + g;
            if (LAYER == 1) {
                int head = blockIdx.x * 2 + warp_n;
                if (row0 < M)     { g_als1[row0 * 4 + head] = ss0; g_ald1[row0 * 4 + head] = dd0; }
                if (row0 + 8 < M) { g_als1[(row0 + 8) * 4 + head] = ss1; g_ald1[(row0 + 8) * 4 + head] = dd1; }
            } else {
                if (row0 < M)     { atomicAdd(&g_als2[row0], ss0); atomicAdd(&g_ald2[row0], dd0); }
                if (row0 + 8 < M) { atomicAdd(&g_als2[row0 + 8], ss1); atomicAdd(&g_ald2[row0 + 8], dd1); }
            }
        }
    }
}

__global__ void __launch_bounds__(256, 2)
gemm1_kernel(const float* __restrict__ x, const float* __restrict__ W1,
             const float* __restrict__ as1, const float* __restrict__ ad1) {
    gemm_tf32_body<128, FIN, 1>(x, W1, g_h1b, as1, ad1, NN, C1);
}
__global__ void __launch_bounds__(256, 2)
gemm2_kernel(const float* __restrict__ W2,
             const float* __restrict__ as2, const float* __restrict__ ad2) {
    gemm_tf32_body<64, C1, 2>(g_out1, W2, g_h2b, as2, ad2, NN, HIDD);
}

// ---- layer-1 aggregation: ONE warp per dst node, elist software-pipelined ----
__global__ void agg1_kernel(const float* __restrict__ b1) {
    int n = (blockIdx.x * blockDim.x + threadIdx.x) >> 5;
    int lane = threadIdx.x & 31;
    if (n >= NN) return;
    int beg = g_row[n], end = g_row[n + 1];
    int h = lane >> 3;
    float ald = g_ald1[n * 4 + h];
    float ce  = g_scal[1 + h];
    float4 acc0 = make_float4(0.f, 0.f, 0.f, 0.f);
    float4 acc1 = make_float4(0.f, 0.f, 0.f, 0.f);
    float den = 0.f;
    int nbatch = (end - beg) >> 2;
    int j = beg;
    int2 sen[4];
    if (nbatch > 0) {
#pragma unroll
        for (int q = 0; q < 4; q++) sen[q] = g_elist[beg + q];
    }
    for (int b = 0; b < nbatch; b++) {
        int2 se[4];
#pragma unroll
        for (int q = 0; q < 4; q++) se[q] = sen[q];
        j += 4;
        if (b + 1 < nbatch) {
#pragma unroll
            for (int q = 0; q < 4; q++) sen[q] = g_elist[j + q];   // prefetch next batch
        }
        uint4 p[4]; float al[4];
#pragma unroll
        for (int q = 0; q < 4; q++) {
            p[q]  = ((const uint4*)(g_h1b + (size_t)se[q].x * (C1 / 2)))[lane];
            al[q] = g_als1[se[q].x * 4 + h];
        }
        float ex[4];
#pragma unroll
        for (int q = 0; q < 4; q++) {
            float z = al[q] + ald + __int_as_float(se[q].y) * ce;
            z = z > 0.f ? z : 0.2f * z;
            ex[q] = __expf(z);
        }
#pragma unroll
        for (int q = 0; q < 4; q++) {
            float2 f0 = unpack_bf16(p[q].x), f1 = unpack_bf16(p[q].y);
            float2 f2 = unpack_bf16(p[q].z), f3 = unpack_bf16(p[q].w);
            den += ex[q];
            acc0.x += ex[q] * f0.x; acc0.y += ex[q] * f0.y;
            acc0.z += ex[q] * f1.x; acc0.w += ex[q] * f1.y;
            acc1.x += ex[q] * f2.x; acc1.y += ex[q] * f2.y;
            acc1.z += ex[q] * f3.x; acc1.w += ex[q] * f3.y;
        }
    }
    for (; j < end; j++) {
        int2 se = g_elist[j];
        uint4 p = ((const uint4*)(g_h1b + (size_t)se.x * (C1 / 2)))[lane];
        float z = g_als1[se.x * 4 + h] + ald + __int_as_float(se.y) * ce;
        z = z > 0.f ? z : 0.2f * z;
        float ex = __expf(z);
        float2 f0 = unpack_bf16(p.x), f1 = unpack_bf16(p.y);
        float2 f2 = unpack_bf16(p.z), f3 = unpack_bf16(p.w);
        den += ex;
        acc0.x += ex * f0.x; acc0.y += ex * f0.y;
        acc0.z += ex * f1.x; acc0.w += ex * f1.y;
        acc1.x += ex * f2.x; acc1.y += ex * f2.y;
        acc1.z += ex * f3.x; acc1.w += ex * f3.y;
    }
    float inv = 1.f / (den + 1e-16f);
    const float4* bp = (const float4*)b1;
    float4 bb0 = bp[lane * 2], bb1 = bp[lane * 2 + 1];
    float4 o0, o1;
    o0.x = fmaxf(acc0.x * inv + bb0.x, 0.f);
    o0.y = fmaxf(acc0.y * inv + bb0.y, 0.f);
    o0.z = fmaxf(acc0.z * inv + bb0.z, 0.f);
    o0.w = fmaxf(acc0.w * inv + bb0.w, 0.f);
    o1.x = fmaxf(acc1.x * inv + bb1.x, 0.f);
    o1.y = fmaxf(acc1.y * inv + bb1.y, 0.f);
    o1.z = fmaxf(acc1.z * inv + bb1.z, 0.f);
    o1.w = fmaxf(acc1.w * inv + bb1.w, 0.f);
    float4* op = (float4*)(g_out1 + (size_t)n * C1);
    op[lane * 2] = o0;
    op[lane * 2 + 1] = o1;
}

// ---- layer-2 aggregation: ONE warp per node, pipelined + LN + pool ----
__global__ void agg2_ln_pool_kernel(const float* __restrict__ b2,
                                    const float* __restrict__ lng,
                                    const float* __restrict__ lnb,
                                    const int* __restrict__ batch) {
    int n = (blockIdx.x * blockDim.x + threadIdx.x) >> 5;
    int lane = threadIdx.x & 31;
    if (n >= NN) return;
    int beg = g_row[n], end = g_row[n + 1];
    float ald = g_ald2[n];
    float ce  = g_scal[5];
    float2 acc = make_float2(0.f, 0.f);
    float den = 0.f;
    int nbatch = (end - beg) >> 2;
    int j = beg;
    int2 sen[4];
    if (nbatch > 0) {
#pragma unroll
        for (int q = 0; q < 4; q++) sen[q] = g_elist[beg + q];
    }
    for (int b = 0; b < nbatch; b++) {
        int2 se[4];
#pragma unroll
        for (int q = 0; q < 4; q++) se[q] = sen[q];
        j += 4;
        if (b + 1 < nbatch) {
#pragma unroll
            for (int q = 0; q < 4; q++) sen[q] = g_elist[j + q];
        }
        uint32_t p[4]; float al[4];
#pragma unroll
        for (int q = 0; q < 4; q++) {
            p[q]  = (g_h2b + (size_t)se[q].x * (HIDD / 2))[lane];
            al[q] = g_als2[se[q].x];
        }
        float ex[4];
#pragma unroll
        for (int q = 0; q < 4; q++) {
            float z = al[q] + ald + __int_as_float(se[q].y) * ce;
            z = z > 0.f ? z : 0.2f * z;
            ex[q] = __expf(z);
        }
#pragma unroll
        for (int q = 0; q < 4; q++) {
            float2 f = unpack_bf16(p[q]);
            den += ex[q];
            acc.x += ex[q] * f.x;
            acc.y += ex[q] * f.y;
        }
    }
    for (; j < end; j++) {
        int2 se = g_elist[j];
        uint32_t p = (g_h2b + (size_t)se.x * (HIDD / 2))[lane];
        float z = g_als2[se.x] + ald + __int_as_float(se.y) * ce;
        z = z > 0.f ? z : 0.2f * z;
        float ex = __expf(z);
        float2 f = unpack_bf16(p);
        den += ex;
        acc.x += ex * f.x;
        acc.y += ex * f.y;
    }
    float inv = 1.f / (den + 1e-16f);
    float2 bb = ((const float2*)b2)[lane];
    float vx = acc.x * inv + bb.x;
    float vy = acc.y * inv + bb.y;
    float s = vx + vy;
    for (int o = 16; o; o >>= 1) s += __shfl_xor_sync(0xffffffffu, s, o);
    float mu = s * (1.0f / 64.0f);
    float dx = vx - mu, dy = vy - mu;
    float q = dx * dx + dy * dy;
    for (int o = 16; o; o >>= 1) q += __shfl_xor_sync(0xffffffffu, q, o);
    float r = rsqrtf(q * (1.0f / 64.0f) + 1e-5f);
    float y0 = dx * r * lng[lane * 2]     + lnb[lane * 2];
    float y1 = dy * r * lng[lane * 2 + 1] + lnb[lane * 2 + 1];
    int g = batch[n];
    atomicAdd(&g_sums[g * 64 + lane * 2],     y0);
    atomicAdd(&g_sums[g * 64 + lane * 2 + 1], y1);
    if (lane == 0) atomicAdd(&g_cnt[g], 1.0f);
}

// ---------------- per-graph MLP head (block per graph, 64 threads) ----------------
__global__ void mlp_kernel(const float* __restrict__ clin, const float* __restrict__ met,
                           const float* __restrict__ Wf1, const float* __restrict__ bf1,
                           const float* __restrict__ Wf2, const float* __restrict__ bf2,
                           const float* __restrict__ Wr,  const float* __restrict__ br,
                           float* __restrict__ out) {
    int g = blockIdx.x, t = threadIdx.x;   // 64 threads
    __shared__ float fused[FUSED_IN];
    __shared__ float l1[64];
    __shared__ float l2[32];
    float cnt = g_cnt[g]; cnt = cnt > 1.f ? cnt : 1.f;
    float e = g_sums[g * 64 + t] / cnt;
    fused[t] = e;
    out[GG + g * 64 + t] = e;              // graph_embedding at offset 64
    if (t < 32) fused[64 + t] = clin[g * 32 + t];
    fused[96 + t]  = met[g * 128 + t];
    fused[160 + t] = met[g * 128 + 64 + t];
    __syncthreads();
    float acc = bf1[t];
#pragma unroll 8
    for (int k = 0; k < FUSED_IN; k++) acc += fused[k] * Wf1[k * 64 + t];
    l1[t] = acc > 0.f ? acc : 0.f;
    __syncthreads();
    if (t < 32) {
        float a2 = bf2[t];
#pragma unroll 8
        for (int j = 0; j < 64; j++) a2 += l1[j] * Wf2[j * 32 + t];
        a2 = a2 > 0.f ? a2 : 0.f;
        l2[t] = a2;
        out[GG + GG * 64 + g * 32 + t] = a2;   // latent at offset 64 + 4096
    }
    __syncthreads();
    if (t == 0) {
        float r = br[0];
#pragma unroll
        for (int j = 0; j < 32; j++) r += l2[j] * Wr[j];
        out[g] = r;                        // risk at offset 0
    }
}

// ---------------- launch ----------------
extern "C" void kernel_launch(void* const* d_in, const int* in_sizes, int n_in,
                              void* d_out, int out_size) {
    const float* x    = (const float*)d_in[0];
    const int*   ei   = (const int*)d_in[1];
    const float* ea   = (const float*)d_in[2];
    const int*   bat  = (const int*)d_in[3];
    const float* clin = (const float*)d_in[4];
    const float* met  = (const float*)d_in[5];
    const float* W1   = (const float*)d_in[6];
    const float* as1  = (const float*)d_in[7];
    const float* ad1  = (const float*)d_in[8];
    const float* ae1  = (const float*)d_in[9];
    const float* We1  = (const float*)d_in[10];
    const float* b1   = (const float*)d_in[11];
    const float* W2   = (const float*)d_in[12];
    const float* as2  = (const float*)d_in[13];
    const float* ad2  = (const float*)d_in[14];
    const float* ae2  = (const float*)d_in[15];
    const float* We2  = (const float*)d_in[16];
    const float* b2   = (const float*)d_in[17];
    const float* lng  = (const float*)d_in[18];
    const float* lnb  = (const float*)d_in[19];
    const float* Wf1  = (const float*)d_in[20];
    const float* bf1  = (const float*)d_in[21];
    const float* Wf2  = (const float*)d_in[22];
    const float* bf2  = (const float*)d_in[23];
    const float* Wr   = (const float*)d_in[24];
    const float* br   = (const float*)d_in[25];
    float* out = (float*)d_out;

    // fork: CSR chain on side stream, GEMM(+logits) on main stream
    cudaStream_t s2;
    cudaEvent_t e0, e1;
    cudaStreamCreateWithFlags(&s2, cudaStreamNonBlocking);
    cudaEventCreateWithFlags(&e0, cudaEventDisableTiming);
    cudaEventCreateWithFlags(&e1, cudaEventDisableTiming);

    cudaEventRecord(e0, 0);
    cudaStreamWaitEvent(s2, e0, 0);

    prep_kernel<<<512, 256, 0, s2>>>(ea);                        // 0
    hist_kernel<<<(ELOOP + 255) / 256, 256, 0, s2>>>(ei);        // 1
    scan1_kernel<<<NB, 256, 0, s2>>>();                          // 2
    gemm1_kernel<<<dim3(C1 / 128, (NN + 127) / 128), 256>>>(x, W1, as1, ad1); // 3 (profiled)
    scan2_kernel<<<1, 256, 0, s2>>>(We1, ae1, We2, ae2);         // 4
    scan3_kernel<<<NB, 256, 0, s2>>>();                          // 5
    scatter_kernel<<<(ELOOP + 255) / 256, 256, 0, s2>>>(ei, ea); // 6
    cudaEventRecord(e1, s2);
    cudaStreamWaitEvent(0, e1, 0);

    // layer 1 aggregation (needs CSR + gemm1 logits): 1 warp/node
    agg1_kernel<<<(NN * 32 + 255) / 256, 256>>>(b1);

    // layer 2 (gemm2 fuses logits2; g_als2/g_ald2 zeroed by prep)
    gemm2_kernel<<<dim3(1, (NN + 127) / 128), 256>>>(W2, as2, ad2);
    agg2_ln_pool_kernel<<<(NN * 32 + 255) / 256, 256>>>(b2, lng, lnb, bat);

    // head
    mlp_kernel<<<GG, 64>>>(clin, met, Wf1, bf1, Wf2, bf2, Wr, br, out);
    // streams/events intentionally not destroyed (graph may reference them)
}

// round 14
// speedup vs baseline: 1.1243x; 1.0366x over previous
#include <cuda_runtime.h>
#include <cuda_bf16.h>
#include <cstdint>

// ---------------- fixed problem shapes ----------------
#define NN      50000
#define EE      800000
#define ELOOP   850000        // EE + NN self loops
#define GG      64
#define FIN     128
#define HIDD    64
#define HEADS   4
#define C1      256           // HEADS*HIDD
#define CLIN    32
#define MET     128
#define FUSED_IN 224          // HID + CLIN + MET
#define NB      196           // ceil(NN/256) scan blocks

// ---------------- device scratch (no allocs allowed) ----------------
__device__ uint32_t g_h1b [(size_t)NN * (C1/2)];  // bf16x2 packed h1 (agg gather)
__device__ float    g_out1[(size_t)NN * C1];      // layer1 output (post bias+relu)
__device__ uint32_t g_h2b [(size_t)NN * (HIDD/2)];// bf16x2 packed h2
__device__ float g_als1[NN * HEADS];
__device__ float g_ald1[NN * HEADS];
__device__ float g_als2[NN];
__device__ float g_ald2[NN];
__device__ float g_sums[GG * HIDD];
__device__ float g_cnt [GG];
__device__ float g_scal[8];     // [0]=sum(edge_attr), [1..4]=ce1[h], [5]=ce2
__device__ float g_part[512];   // per-block partial sums of edge_attr
// CSR by destination
__device__ int  g_row [NN + 1];
__device__ int  g_cur [NN];     // hist -> degree -> cursor
__device__ int  g_bsum[256];    // per-scan-block degree sums
__device__ int  g_boff[256];    // exclusive block offsets
__device__ int2 g_elist[ELOOP]; // (src, float_bits(edge_attr)) sorted by dst

__device__ __forceinline__ uint32_t pack_bf16(float a, float b) {
    __nv_bfloat162 h = __float22bfloat162_rn(make_float2(a, b));
    return *reinterpret_cast<uint32_t*>(&h);
}
__device__ __forceinline__ float2 unpack_bf16(uint32_t u) {
    return __bfloat1622float2(*reinterpret_cast<__nv_bfloat162*>(&u));
}

__device__ __forceinline__ void cp_async16(uint32_t saddr, const void* gptr) {
    asm volatile("cp.async.cg.shared.global [%0], [%1], 16;" :: "r"(saddr), "l"(gptr));
}
__device__ __forceinline__ void cp_commit() {
    asm volatile("cp.async.commit_group;");
}
template<int N>
__device__ __forceinline__ void cp_wait() {
    asm volatile("cp.async.wait_group %0;" :: "n"(N));
}

// ---------------- prep: zero scratch + partial sums of edge_attr ----------------
__global__ void prep_kernel(const float* __restrict__ ea) {
    __shared__ float sh[8];
    int i = blockIdx.x * blockDim.x + threadIdx.x;
    if (i < NN) { g_cur[i] = 0; g_als2[i] = 0.f; g_ald2[i] = 0.f; }
    if (i < GG * HIDD) g_sums[i] = 0.f;
    if (i < GG) g_cnt[i] = 0.f;
    if (i < 8)  g_scal[i] = 0.f;
    float s = 0.f;
    for (size_t e = i; e < EE; e += (size_t)512 * 256) s += ea[e];
    for (int o = 16; o; o >>= 1) s += __shfl_xor_sync(0xffffffffu, s, o);
    if ((threadIdx.x & 31) == 0) sh[threadIdx.x >> 5] = s;
    __syncthreads();
    if (threadIdx.x < 8) {
        float v = sh[threadIdx.x];
        for (int o = 4; o; o >>= 1) v += __shfl_xor_sync(0xffu, v, o);
        if (threadIdx.x == 0) g_part[blockIdx.x] = v;
    }
}

// ---------------- CSR build: histogram of dst ----------------
__global__ void hist_kernel(const int* __restrict__ ei) {
    int e = blockIdx.x * blockDim.x + threadIdx.x;
    if (e >= ELOOP) return;
    int d = (e < EE) ? ei[EE + e] : (e - EE);
    atomicAdd(&g_cur[d], 1);
}

// ---------------- scan stage 1: per-block degree sums ----------------
__global__ void scan1_kernel() {
    __shared__ int sh[8];
    int idx = blockIdx.x * 256 + threadIdx.x;
    int v = (idx < NN) ? g_cur[idx] : 0;
    int s = v;
    for (int o = 16; o; o >>= 1) s += __shfl_xor_sync(0xffffffffu, s, o);
    if ((threadIdx.x & 31) == 0) sh[threadIdx.x >> 5] = s;
    __syncthreads();
    if (threadIdx.x < 8) {
        int u = sh[threadIdx.x];
        for (int o = 4; o; o >>= 1) u += __shfl_xor_sync(0xffu, u, o);
        if (threadIdx.x == 0) g_bsum[blockIdx.x] = u;
    }
}

// ---- scan stage 2 (1 block x 256): block-offset scan + mean finalize + ce dots ----
__global__ void scan2_kernel(const float* __restrict__ We1, const float* __restrict__ ae1,
                             const float* __restrict__ We2, const float* __restrict__ ae2) {
    __shared__ int ss[256];
    __shared__ float fs[8];
    int t = threadIdx.x;
    float v = g_part[t] + g_part[t + 256];
    for (int o = 16; o; o >>= 1) v += __shfl_xor_sync(0xffffffffu, v, o);
    if ((t & 31) == 0) fs[t >> 5] = v;
    __syncthreads();
    if (t < 8) {
        float u = fs[t];
        for (int o = 4; o; o >>= 1) u += __shfl_xor_sync(0xffu, u, o);
        if (t == 0) g_scal[0] = u;
    }
    atomicAdd(&g_scal[1 + (t >> 6)], We1[t] * ae1[t]);
    if (t < 64) atomicAdd(&g_scal[5], We2[t] * ae2[t]);
    int b = (t < NB) ? g_bsum[t] : 0;
    ss[t] = b;
    __syncthreads();
    for (int off = 1; off < 256; off <<= 1) {
        int w = (t >= off) ? ss[t - off] : 0;
        __syncthreads();
        ss[t] += w;
        __syncthreads();
    }
    if (t < NB) g_boff[t] = ss[t] - b;
    if (t == 0) g_row[NN] = ELOOP;
}

// ---- scan stage 3: per-block exclusive scan + writeback ----
__global__ void scan3_kernel() {
    __shared__ int ss[256];
    int t = threadIdx.x;
    int idx = blockIdx.x * 256 + t;
    int d = (idx < NN) ? g_cur[idx] : 0;
    ss[t] = d;
    __syncthreads();
    for (int off = 1; off < 256; off <<= 1) {
        int w = (t >= off) ? ss[t - off] : 0;
        __syncthreads();
        ss[t] += w;
        __syncthreads();
    }
    int excl = ss[t] - d + g_boff[blockIdx.x];
    if (idx < NN) {
        g_row[idx] = excl;
        g_cur[idx] = excl;
    }
}

// ---------------- CSR build: scatter (src, edge_attr) ----------------
__global__ void scatter_kernel(const int* __restrict__ ei, const float* __restrict__ ea) {
    int e = blockIdx.x * blockDim.x + threadIdx.x;
    if (e >= ELOOP) return;
    int s, d; float att;
    if (e < EE) { s = ei[e]; d = ei[EE + e]; att = ea[e]; }
    else        { s = d = e - EE; att = g_scal[0] * (1.0f / EE); }
    int pos = atomicAdd(&g_cur[d], 1);
    g_elist[pos] = make_int2(s, __float_as_int(att));
}

// ---- TF32 GEMM, double-buffered, bf16 output + FUSED attention logits ----
template<int BN, int K, int LAYER>
__device__ __forceinline__ void gemm_tf32_body(const float* __restrict__ A,
                                               const float* __restrict__ B,
                                               uint32_t* __restrict__ Cb,
                                               const float* __restrict__ avS,
                                               const float* __restrict__ avD,
                                               int M, int Ncol) {
    constexpr int NF = BN / 16;
    __shared__ uint32_t As[2][128][20];
    __shared__ uint32_t Bs[2][16][BN + 8];
    int tid = threadIdx.x;
    int warp = tid >> 5, lane = tid & 31;
    int warp_m = warp & 3;
    int warp_n = warp >> 2;
    int m0 = blockIdx.y * 128, n0 = blockIdx.x * BN;
    int g = lane >> 2, t4 = lane & 3;

    int arow = tid >> 1, acb = (tid & 1) * 8;
    int brow = tid >> 4;
    int bcb  = (BN == 128) ? (tid & 15) * 8 : (tid & 15) * 4;

    float acc[2][NF][4];
#pragma unroll
    for (int mf = 0; mf < 2; mf++)
#pragma unroll
        for (int nf = 0; nf < NF; nf++)
#pragma unroll
            for (int i = 0; i < 4; i++) acc[mf][nf][i] = 0.f;

    float4 pa0, pa1, pb0, pb1;
    auto load_tile = [&](int k0) {
        pa0 = make_float4(0.f, 0.f, 0.f, 0.f);
        pa1 = make_float4(0.f, 0.f, 0.f, 0.f);
        if (m0 + arow < M) {
            const float* p = A + (size_t)(m0 + arow) * K + k0 + acb;
            pa0 = *(const float4*)p;
            pa1 = *(const float4*)(p + 4);
        }
        const float* q = B + (size_t)(k0 + brow) * Ncol + n0 + bcb;
        pb0 = *(const float4*)q;
        if (BN == 128) pb1 = *(const float4*)(q + 4);
    };
    auto store_tile = [&](int buf) {
        *(uint4*)&As[buf][arow][acb]     = *reinterpret_cast<uint4*>(&pa0);
        *(uint4*)&As[buf][arow][acb + 4] = *reinterpret_cast<uint4*>(&pa1);
        *(uint4*)&Bs[buf][brow][bcb]     = *reinterpret_cast<uint4*>(&pb0);
        if (BN == 128)
            *(uint4*)&Bs[buf][brow][bcb + 4] = *reinterpret_cast<uint4*>(&pb1);
    };
    auto compute = [&](int buf) {
#pragma unroll
        for (int ks = 0; ks < 16; ks += 8) {
            uint32_t a[2][4];
#pragma unroll
            for (int mf = 0; mf < 2; mf++) {
                int rb = warp_m * 32 + mf * 16;
                a[mf][0] = As[buf][rb + g][ks + t4];
                a[mf][1] = As[buf][rb + 8 + g][ks + t4];
                a[mf][2] = As[buf][rb + g][ks + 4 + t4];
                a[mf][3] = As[buf][rb + 8 + g][ks + 4 + t4];
            }
#pragma unroll
            for (int nf = 0; nf < NF; nf++) {
                int cb = warp_n * (BN / 2) + nf * 8;
                uint32_t b0 = Bs[buf][ks + t4][cb + g];
                uint32_t b1 = Bs[buf][ks + 4 + t4][cb + g];
#pragma unroll
                for (int mf = 0; mf < 2; mf++) {
                    asm volatile(
                        "mma.sync.aligned.m16n8k8.row.col.f32.tf32.tf32.f32 "
                        "{%0,%1,%2,%3}, {%4,%5,%6,%7}, {%8,%9}, {%0,%1,%2,%3};"
                        : "+f"(acc[mf][nf][0]), "+f"(acc[mf][nf][1]),
                          "+f"(acc[mf][nf][2]), "+f"(acc[mf][nf][3])
                        : "r"(a[mf][0]), "r"(a[mf][1]), "r"(a[mf][2]), "r"(a[mf][3]),
                          "r"(b0), "r"(b1));
                }
            }
        }
    };

    load_tile(0);
    store_tile(0);
    __syncthreads();
    int cur = 0;
    for (int k0 = 0; k0 < K; k0 += 16) {
        bool more = (k0 + 16 < K);
        if (more) load_tile(k0 + 16);
        compute(cur);
        if (more) store_tile(cur ^ 1);
        __syncthreads();
        cur ^= 1;
    }

    // ---- bf16 store ----
#pragma unroll
    for (int mf = 0; mf < 2; mf++) {
#pragma unroll
        for (int nf = 0; nf < NF; nf++) {
            int row0 = m0 + warp_m * 32 + mf * 16 + g;
            int col  = n0 + warp_n * (BN / 2) + nf * 8 + 2 * t4;
            if (row0 < M)
                Cb[(size_t)row0 * (Ncol / 2) + col / 2] = pack_bf16(acc[mf][nf][0], acc[mf][nf][1]);
            if (row0 + 8 < M)
                Cb[(size_t)(row0 + 8) * (Ncol / 2) + col / 2] = pack_bf16(acc[mf][nf][2], acc[mf][nf][3]);
        }
    }

    // ---- fused attention logits ----
    float2 wS[NF], wD[NF];
    int cbase = (LAYER == 1) ? ((blockIdx.x * 2 + warp_n) * 64) : (warp_n * (BN / 2));
#pragma unroll
    for (int nf = 0; nf < NF; nf++) {
        int c = cbase + nf * 8 + 2 * t4;
        wS[nf] = *(const float2*)(avS + c);
        wD[nf] = *(const float2*)(avD + c);
    }
#pragma unroll
    for (int mf = 0; mf < 2; mf++) {
        float ss0 = 0.f, dd0 = 0.f, ss1 = 0.f, dd1 = 0.f;
#pragma unroll
        for (int nf = 0; nf < NF; nf++) {
            ss0 += acc[mf][nf][0] * wS[nf].x + acc[mf][nf][1] * wS[nf].y;
            dd0 += acc[mf][nf][0] * wD[nf].x + acc[mf][nf][1] * wD[nf].y;
            ss1 += acc[mf][nf][2] * wS[nf].x + acc[mf][nf][3] * wS[nf].y;
            dd1 += acc[mf][nf][2] * wD[nf].x + acc[mf][nf][3] * wD[nf].y;
        }
        ss0 += __shfl_xor_sync(0xffffffffu, ss0, 1); ss0 += __shfl_xor_sync(0xffffffffu, ss0, 2);
        dd0 += __shfl_xor_sync(0xffffffffu, dd0, 1); dd0 += __shfl_xor_sync(0xffffffffu, dd0, 2);
        ss1 += __shfl_xor_sync(0xffffffffu, ss1, 1); ss1 += __shfl_xor_sync(0xffffffffu, ss1, 2);
        dd1 += __shfl_xor_sync(0xffffffffu, dd1, 1); dd1 += __shfl_xor_sync(0xffffffffu, dd1, 2);
        if (t4 == 0) {
            int row0 = m0 + warp_m * 32 + mf * 16 + g;
            if (LAYER == 1) {
                int head = blockIdx.x * 2 + warp_n;
                if (row0 < M)     { g_als1[row0 * 4 + head] = ss0; g_ald1[row0 * 4 + head] = dd0; }
                if (row0 + 8 < M) { g_als1[(row0 + 8) * 4 + head] = ss1; g_ald1[(row0 + 8) * 4 + head] = dd1; }
            } else {
                if (row0 < M)     { atomicAdd(&g_als2[row0], ss0); atomicAdd(&g_ald2[row0], dd0); }
                if (row0 + 8 < M) { atomicAdd(&g_als2[row0 + 8], ss1); atomicAdd(&g_ald2[row0 + 8], dd1); }
            }
        }
    }
}

__global__ void __launch_bounds__(256, 2)
gemm1_kernel(const float* __restrict__ x, const float* __restrict__ W1,
             const float* __restrict__ as1, const float* __restrict__ ad1) {
    gemm_tf32_body<128, FIN, 1>(x, W1, g_h1b, as1, ad1, NN, C1);
}
__global__ void __launch_bounds__(256, 2)
gemm2_kernel(const float* __restrict__ W2,
             const float* __restrict__ as2, const float* __restrict__ ad2) {
    gemm_tf32_body<64, C1, 2>(g_out1, W2, g_h2b, as2, ad2, NN, HIDD);
}

// ---- layer-1 aggregation: warp per node, cp.async double-buffered gather ----
// smem: 8 warps x 2 stages x 4 edges x 32 lanes x 16B = 32 KB/block.
__global__ void agg1_kernel(const float* __restrict__ b1) {
    __shared__ uint4 s_p[8][2][4][32];
    int wid = threadIdx.x >> 5;
    int lane = threadIdx.x & 31;
    int n = (blockIdx.x * blockDim.x + threadIdx.x) >> 5;
    if (n >= NN) return;
    int beg = g_row[n], end = g_row[n + 1];
    int h = lane >> 3;
    float ald = g_ald1[n * 4 + h];
    float ce  = g_scal[1 + h];
    float4 acc0 = make_float4(0.f, 0.f, 0.f, 0.f);
    float4 acc1 = make_float4(0.f, 0.f, 0.f, 0.f);
    float den = 0.f;
    int nbatch = (end - beg) >> 2;
    uint32_t sbase = (uint32_t)__cvta_generic_to_shared(&s_p[wid][0][0][lane]);
    // strides in bytes: stage = 4*32*16 = 2048, edge = 32*16 = 512
    int2 se_cur[4], se_nxt[4];
    float al_cur[4], al_nxt[4];
    int j = beg;
    if (nbatch > 0) {
#pragma unroll
        for (int q = 0; q < 4; q++) {
            se_cur[q] = g_elist[j + q];
            al_cur[q] = g_als1[se_cur[q].x * 4 + h];
            cp_async16(sbase + q * 512,
                       (const char*)g_h1b + (((size_t)se_cur[q].x * (C1 / 2) + lane * 4) << 2));
        }
        cp_commit();
        j += 4;
    }
    for (int b = 0; b < nbatch; b++) {
        int stage = b & 1;
        bool more = (b + 1 < nbatch);
        if (more) {
#pragma unroll
            for (int q = 0; q < 4; q++) {
                se_nxt[q] = g_elist[j + q];
                al_nxt[q] = g_als1[se_nxt[q].x * 4 + h];
                cp_async16(sbase + (stage ^ 1) * 2048 + q * 512,
                           (const char*)g_h1b + (((size_t)se_nxt[q].x * (C1 / 2) + lane * 4) << 2));
            }
            cp_commit();
            j += 4;
            cp_wait<1>();
        } else {
            cp_wait<0>();
        }
#pragma unroll
        for (int q = 0; q < 4; q++) {
            uint4 p = s_p[wid][stage][q][lane];
            float z = al_cur[q] + ald + __int_as_float(se_cur[q].y) * ce;
            z = z > 0.f ? z : 0.2f * z;
            float ex = __expf(z);
            float2 f0 = unpack_bf16(p.x), f1 = unpack_bf16(p.y);
            float2 f2 = unpack_bf16(p.z), f3 = unpack_bf16(p.w);
            den += ex;
            acc0.x += ex * f0.x; acc0.y += ex * f0.y;
            acc0.z += ex * f1.x; acc0.w += ex * f1.y;
            acc1.x += ex * f2.x; acc1.y += ex * f2.y;
            acc1.z += ex * f3.x; acc1.w += ex * f3.y;
        }
        if (more) {
#pragma unroll
            for (int q = 0; q < 4; q++) { se_cur[q] = se_nxt[q]; al_cur[q] = al_nxt[q]; }
        }
    }
    // remainder edges (direct LDG)
    for (int r = beg + (nbatch << 2); r < end; r++) {
        int2 se = g_elist[r];
        uint4 p = ((const uint4*)(g_h1b + (size_t)se.x * (C1 / 2)))[lane];
        float z = g_als1[se.x * 4 + h] + ald + __int_as_float(se.y) * ce;
        z = z > 0.f ? z : 0.2f * z;
        float ex = __expf(z);
        float2 f0 = unpack_bf16(p.x), f1 = unpack_bf16(p.y);
        float2 f2 = unpack_bf16(p.z), f3 = unpack_bf16(p.w);
        den += ex;
        acc0.x += ex * f0.x; acc0.y += ex * f0.y;
        acc0.z += ex * f1.x; acc0.w += ex * f1.y;
        acc1.x += ex * f2.x; acc1.y += ex * f2.y;
        acc1.z += ex * f3.x; acc1.w += ex * f3.y;
    }
    float inv = 1.f / (den + 1e-16f);
    const float4* bp = (const float4*)b1;
    float4 bb0 = bp[lane * 2], bb1 = bp[lane * 2 + 1];
    float4 o0, o1;
    o0.x = fmaxf(acc0.x * inv + bb0.x, 0.f);
    o0.y = fmaxf(acc0.y * inv + bb0.y, 0.f);
    o0.z = fmaxf(acc0.z * inv + bb0.z, 0.f);
    o0.w = fmaxf(acc0.w * inv + bb0.w, 0.f);
    o1.x = fmaxf(acc1.x * inv + bb1.x, 0.f);
    o1.y = fmaxf(acc1.y * inv + bb1.y, 0.f);
    o1.z = fmaxf(acc1.z * inv + bb1.z, 0.f);
    o1.w = fmaxf(acc1.w * inv + bb1.w, 0.f);
    float4* op = (float4*)(g_out1 + (size_t)n * C1);
    op[lane * 2] = o0;
    op[lane * 2 + 1] = o1;
}

// ---- layer-2 aggregation (R10 known-good form) + bias + LayerNorm + pool ----
__global__ void agg2_ln_pool_kernel(const float* __restrict__ b2,
                                    const float* __restrict__ lng,
                                    const float* __restrict__ lnb,
                                    const int* __restrict__ batch) {
    int n = (blockIdx.x * blockDim.x + threadIdx.x) >> 5;
    int lane = threadIdx.x & 31;
    if (n >= NN) return;
    int beg = g_row[n], end = g_row[n + 1];
    float ald = g_ald2[n];
    float ce  = g_scal[5];
    float2 acc = make_float2(0.f, 0.f);
    float den = 0.f;
    int j = beg;
    for (; j + 4 <= end; j += 4) {
        int2 se[4];
#pragma unroll
        for (int q = 0; q < 4; q++) se[q] = g_elist[j + q];
        uint32_t p[4]; float al[4];
#pragma unroll
        for (int q = 0; q < 4; q++) {
            p[q]  = (g_h2b + (size_t)se[q].x * (HIDD / 2))[lane];
            al[q] = g_als2[se[q].x];
        }
        float ex[4];
#pragma unroll
        for (int q = 0; q < 4; q++) {
            float z = al[q] + ald + __int_as_float(se[q].y) * ce;
            z = z > 0.f ? z : 0.2f * z;
            ex[q] = __expf(z);
        }
#pragma unroll
        for (int q = 0; q < 4; q++) {
            float2 f = unpack_bf16(p[q]);
            den += ex[q];
            acc.x += ex[q] * f.x;
            acc.y += ex[q] * f.y;
        }
    }
    for (; j < end; j++) {
        int2 se = g_elist[j];
        uint32_t p = (g_h2b + (size_t)se.x * (HIDD / 2))[lane];
        float z = g_als2[se.x] + ald + __int_as_float(se.y) * ce;
        z = z > 0.f ? z : 0.2f * z;
        float ex = __expf(z);
        float2 f = unpack_bf16(p);
        den += ex;
        acc.x += ex * f.x;
        acc.y += ex * f.y;
    }
    float inv = 1.f / (den + 1e-16f);
    float2 bb = ((const float2*)b2)[lane];
    float vx = acc.x * inv + bb.x;
    float vy = acc.y * inv + bb.y;
    float s = vx + vy;
    for (int o = 16; o; o >>= 1) s += __shfl_xor_sync(0xffffffffu, s, o);
    float mu = s * (1.0f / 64.0f);
    float dx = vx - mu, dy = vy - mu;
    float q = dx * dx + dy * dy;
    for (int o = 16; o; o >>= 1) q += __shfl_xor_sync(0xffffffffu, q, o);
    float r = rsqrtf(q * (1.0f / 64.0f) + 1e-5f);
    float y0 = dx * r * lng[lane * 2]     + lnb[lane * 2];
    float y1 = dy * r * lng[lane * 2 + 1] + lnb[lane * 2 + 1];
    int g = batch[n];
    atomicAdd(&g_sums[g * 64 + lane * 2],     y0);
    atomicAdd(&g_sums[g * 64 + lane * 2 + 1], y1);
    if (lane == 0) atomicAdd(&g_cnt[g], 1.0f);
}

// ---------------- per-graph MLP head (block per graph, 64 threads) ----------------
__global__ void mlp_kernel(const float* __restrict__ clin, const float* __restrict__ met,
                           const float* __restrict__ Wf1, const float* __restrict__ bf1,
                           const float* __restrict__ Wf2, const float* __restrict__ bf2,
                           const float* __restrict__ Wr,  const float* __restrict__ br,
                           float* __restrict__ out) {
    int g = blockIdx.x, t = threadIdx.x;   // 64 threads
    __shared__ float fused[FUSED_IN];
    __shared__ float l1[64];
    __shared__ float l2[32];
    float cnt = g_cnt[g]; cnt = cnt > 1.f ? cnt : 1.f;
    float e = g_sums[g * 64 + t] / cnt;
    fused[t] = e;
    out[GG + g * 64 + t] = e;              // graph_embedding at offset 64
    if (t < 32) fused[64 + t] = clin[g * 32 + t];
    fused[96 + t]  = met[g * 128 + t];
    fused[160 + t] = met[g * 128 + 64 + t];
    __syncthreads();
    float acc = bf1[t];
#pragma unroll 8
    for (int k = 0; k < FUSED_IN; k++) acc += fused[k] * Wf1[k * 64 + t];
    l1[t] = acc > 0.f ? acc : 0.f;
    __syncthreads();
    if (t < 32) {
        float a2 = bf2[t];
#pragma unroll 8
        for (int j = 0; j < 64; j++) a2 += l1[j] * Wf2[j * 32 + t];
        a2 = a2 > 0.f ? a2 : 0.f;
        l2[t] = a2;
        out[GG + GG * 64 + g * 32 + t] = a2;   // latent at offset 64 + 4096
    }
    __syncthreads();
    if (t == 0) {
        float r = br[0];
#pragma unroll
        for (int j = 0; j < 32; j++) r += l2[j] * Wr[j];
        out[g] = r;                        // risk at offset 0
    }
}

// ---------------- launch ----------------
extern "C" void kernel_launch(void* const* d_in, const int* in_sizes, int n_in,
                              void* d_out, int out_size) {
    const float* x    = (const float*)d_in[0];
    const int*   ei   = (const int*)d_in[1];
    const float* ea   = (const float*)d_in[2];
    const int*   bat  = (const int*)d_in[3];
    const float* clin = (const float*)d_in[4];
    const float* met  = (const float*)d_in[5];
    const float* W1   = (const float*)d_in[6];
    const float* as1  = (const float*)d_in[7];
    const float* ad1  = (const float*)d_in[8];
    const float* ae1  = (const float*)d_in[9];
    const float* We1  = (const float*)d_in[10];
    const float* b1   = (const float*)d_in[11];
    const float* W2   = (const float*)d_in[12];
    const float* as2  = (const float*)d_in[13];
    const float* ad2  = (const float*)d_in[14];
    const float* ae2  = (const float*)d_in[15];
    const float* We2  = (const float*)d_in[16];
    const float* b2   = (const float*)d_in[17];
    const float* lng  = (const float*)d_in[18];
    const float* lnb  = (const float*)d_in[19];
    const float* Wf1  = (const float*)d_in[20];
    const float* bf1  = (const float*)d_in[21];
    const float* Wf2  = (const float*)d_in[22];
    const float* bf2  = (const float*)d_in[23];
    const float* Wr   = (const float*)d_in[24];
    const float* br   = (const float*)d_in[25];
    float* out = (float*)d_out;

    // fork: CSR chain on side stream, GEMM(+logits) on main stream
    cudaStream_t s2;
    cudaEvent_t e0, e1;
    cudaStreamCreateWithFlags(&s2, cudaStreamNonBlocking);
    cudaEventCreateWithFlags(&e0, cudaEventDisableTiming);
    cudaEventCreateWithFlags(&e1, cudaEventDisableTiming);

    cudaEventRecord(e0, 0);
    cudaStreamWaitEvent(s2, e0, 0);

    prep_kernel<<<512, 256, 0, s2>>>(ea);                        // 0
    hist_kernel<<<(ELOOP + 255) / 256, 256, 0, s2>>>(ei);        // 1
    scan1_kernel<<<NB, 256, 0, s2>>>();                          // 2
    gemm1_kernel<<<dim3(C1 / 128, (NN + 127) / 128), 256>>>(x, W1, as1, ad1); // 3 (profiled)
    scan2_kernel<<<1, 256, 0, s2>>>(We1, ae1, We2, ae2);         // 4
    scan3_kernel<<<NB, 256, 0, s2>>>();                          // 5
    scatter_kernel<<<(ELOOP + 255) / 256, 256, 0, s2>>>(ei, ea); // 6
    cudaEventRecord(e1, s2);
    cudaStreamWaitEvent(0, e1, 0);

    // layer 1 aggregation (needs CSR + gemm1 logits): 1 warp/node, cp.async pipelined
    agg1_kernel<<<(NN * 32 + 255) / 256, 256>>>(b1);

    // layer 2 (gemm2 fuses logits2; g_als2/g_ald2 zeroed by prep)
    gemm2_kernel<<<dim3(1, (NN + 127) / 128), 256>>>(W2, as2, ad2);
    agg2_ln_pool_kernel<<<(NN * 32 + 255) / 256, 256>>>(b2, lng, lnb, bat);

    // head
    mlp_kernel<<<GG, 64>>>(clin, met, Wf1, bf1, Wf2, bf2, Wr, br, out);
    // streams/events intentionally not destroyed (graph may reference them)
}

// round 15
// speedup vs baseline: 1.1976x; 1.0652x over previous
#include <cuda_runtime.h>
#include <cuda_bf16.h>
#include <cstdint>

// ---------------- fixed problem shapes ----------------
#define NN      50000
#define EE      800000
#define ELOOP   850000        // EE + NN self loops
#define GG      64
#define FIN     128
#define HIDD    64
#define HEADS   4
#define C1      256           // HEADS*HIDD
#define CLIN    32
#define MET     128
#define FUSED_IN 224          // HID + CLIN + MET
#define NB      196           // ceil(NN/256) scan blocks

// ---------------- device scratch (no allocs allowed) ----------------
__device__ uint32_t g_h1b  [(size_t)NN * (C1/2)];  // bf16x2 packed h1 (agg gather)
__device__ uint32_t g_out1b[(size_t)NN * (C1/2)];  // bf16x2 packed layer1 output
__device__ uint32_t g_h2b  [(size_t)NN * (HIDD/2)];// bf16x2 packed h2
__device__ float g_als1[NN * HEADS];
__device__ float g_ald1[NN * HEADS];
__device__ float g_als2[NN];
__device__ float g_ald2[NN];
__device__ float g_sums[GG * HIDD];
__device__ float g_cnt [GG];
__device__ float g_scal[8];     // [0]=sum(edge_attr), [1..4]=ce1[h], [5]=ce2
__device__ float g_part[512];   // per-block partial sums of edge_attr
// CSR by destination
__device__ int  g_row [NN + 1];
__device__ int  g_cur [NN];     // hist -> degree -> cursor
__device__ int  g_bsum[256];    // per-scan-block degree sums
__device__ int  g_boff[256];    // exclusive block offsets
__device__ int2 g_elist[ELOOP]; // (src, float_bits(edge_attr)) sorted by dst

__device__ __forceinline__ uint32_t pack_bf16(float a, float b) {
    __nv_bfloat162 h = __float22bfloat162_rn(make_float2(a, b));
    return *reinterpret_cast<uint32_t*>(&h);
}
__device__ __forceinline__ float2 unpack_bf16(uint32_t u) {
    return __bfloat1622float2(*reinterpret_cast<__nv_bfloat162*>(&u));
}

// ---------------- prep: zero scratch + partial sums of edge_attr ----------------
__global__ void prep_kernel(const float* __restrict__ ea) {
    __shared__ float sh[8];
    int i = blockIdx.x * blockDim.x + threadIdx.x;
    if (i < NN) { g_cur[i] = 0; g_als2[i] = 0.f; g_ald2[i] = 0.f; }
    if (i < GG * HIDD) g_sums[i] = 0.f;
    if (i < GG) g_cnt[i] = 0.f;
    if (i < 8)  g_scal[i] = 0.f;
    float s = 0.f;
    for (size_t e = i; e < EE; e += (size_t)512 * 256) s += ea[e];
    for (int o = 16; o; o >>= 1) s += __shfl_xor_sync(0xffffffffu, s, o);
    if ((threadIdx.x & 31) == 0) sh[threadIdx.x >> 5] = s;
    __syncthreads();
    if (threadIdx.x < 8) {
        float v = sh[threadIdx.x];
        for (int o = 4; o; o >>= 1) v += __shfl_xor_sync(0xffu, v, o);
        if (threadIdx.x == 0) g_part[blockIdx.x] = v;
    }
}

// ---------------- CSR build: histogram of dst ----------------
__global__ void hist_kernel(const int* __restrict__ ei) {
    int e = blockIdx.x * blockDim.x + threadIdx.x;
    if (e >= ELOOP) return;
    int d = (e < EE) ? ei[EE + e] : (e - EE);
    atomicAdd(&g_cur[d], 1);
}

// ---------------- scan stage 1: per-block degree sums ----------------
__global__ void scan1_kernel() {
    __shared__ int sh[8];
    int idx = blockIdx.x * 256 + threadIdx.x;
    int v = (idx < NN) ? g_cur[idx] : 0;
    int s = v;
    for (int o = 16; o; o >>= 1) s += __shfl_xor_sync(0xffffffffu, s, o);
    if ((threadIdx.x & 31) == 0) sh[threadIdx.x >> 5] = s;
    __syncthreads();
    if (threadIdx.x < 8) {
        int u = sh[threadIdx.x];
        for (int o = 4; o; o >>= 1) u += __shfl_xor_sync(0xffu, u, o);
        if (threadIdx.x == 0) g_bsum[blockIdx.x] = u;
    }
}

// ---- scan stage 2 (1 block x 256): block-offset scan + mean finalize + ce dots ----
__global__ void scan2_kernel(const float* __restrict__ We1, const float* __restrict__ ae1,
                             const float* __restrict__ We2, const float* __restrict__ ae2) {
    __shared__ int ss[256];
    __shared__ float fs[8];
    int t = threadIdx.x;
    float v = g_part[t] + g_part[t + 256];
    for (int o = 16; o; o >>= 1) v += __shfl_xor_sync(0xffffffffu, v, o);
    if ((t & 31) == 0) fs[t >> 5] = v;
    __syncthreads();
    if (t < 8) {
        float u = fs[t];
        for (int o = 4; o; o >>= 1) u += __shfl_xor_sync(0xffu, u, o);
        if (t == 0) g_scal[0] = u;
    }
    atomicAdd(&g_scal[1 + (t >> 6)], We1[t] * ae1[t]);
    if (t < 64) atomicAdd(&g_scal[5], We2[t] * ae2[t]);
    int b = (t < NB) ? g_bsum[t] : 0;
    ss[t] = b;
    __syncthreads();
    for (int off = 1; off < 256; off <<= 1) {
        int w = (t >= off) ? ss[t - off] : 0;
        __syncthreads();
        ss[t] += w;
        __syncthreads();
    }
    if (t < NB) g_boff[t] = ss[t] - b;
    if (t == 0) g_row[NN] = ELOOP;
}

// ---- scan stage 3: per-block exclusive scan + writeback ----
__global__ void scan3_kernel() {
    __shared__ int ss[256];
    int t = threadIdx.x;
    int idx = blockIdx.x * 256 + t;
    int d = (idx < NN) ? g_cur[idx] : 0;
    ss[t] = d;
    __syncthreads();
    for (int off = 1; off < 256; off <<= 1) {
        int w = (t >= off) ? ss[t - off] : 0;
        __syncthreads();
        ss[t] += w;
        __syncthreads();
    }
    int excl = ss[t] - d + g_boff[blockIdx.x];
    if (idx < NN) {
        g_row[idx] = excl;
        g_cur[idx] = excl;
    }
}

// ---------------- CSR build: scatter (src, edge_attr) ----------------
__global__ void scatter_kernel(const int* __restrict__ ei, const float* __restrict__ ea) {
    int e = blockIdx.x * blockDim.x + threadIdx.x;
    if (e >= ELOOP) return;
    int s, d; float att;
    if (e < EE) { s = ei[e]; d = ei[EE + e]; att = ea[e]; }
    else        { s = d = e - EE; att = g_scal[0] * (1.0f / EE); }
    int pos = atomicAdd(&g_cur[d], 1);
    g_elist[pos] = make_int2(s, __float_as_int(att));
}

// ---- TF32 GEMM, double-buffered, bf16 output + FUSED attention logits ----
// LAYER=1: A is fp32 (x). LAYER=2: A is bf16x2-packed (g_out1b).
template<int BN, int K, int LAYER>
__device__ __forceinline__ void gemm_tf32_body(const void* __restrict__ Av,
                                               const float* __restrict__ B,
                                               uint32_t* __restrict__ Cb,
                                               const float* __restrict__ avS,
                                               const float* __restrict__ avD,
                                               int M, int Ncol) {
    constexpr int NF = BN / 16;
    __shared__ uint32_t As[2][128][20];
    __shared__ uint32_t Bs[2][16][BN + 8];
    int tid = threadIdx.x;
    int warp = tid >> 5, lane = tid & 31;
    int warp_m = warp & 3;
    int warp_n = warp >> 2;
    int m0 = blockIdx.y * 128, n0 = blockIdx.x * BN;
    int g = lane >> 2, t4 = lane & 3;

    int arow = tid >> 1, acb = (tid & 1) * 8;   // 8 floats per thread
    int brow = tid >> 4;
    int bcb  = (BN == 128) ? (tid & 15) * 8 : (tid & 15) * 4;

    float acc[2][NF][4];
#pragma unroll
    for (int mf = 0; mf < 2; mf++)
#pragma unroll
        for (int nf = 0; nf < NF; nf++)
#pragma unroll
            for (int i = 0; i < 4; i++) acc[mf][nf][i] = 0.f;

    float4 pa0, pa1, pb0, pb1;
    auto load_tile = [&](int k0) {
        pa0 = make_float4(0.f, 0.f, 0.f, 0.f);
        pa1 = make_float4(0.f, 0.f, 0.f, 0.f);
        if (m0 + arow < M) {
            if (LAYER == 1) {
                const float* p = (const float*)Av + (size_t)(m0 + arow) * K + k0 + acb;
                pa0 = *(const float4*)p;
                pa1 = *(const float4*)(p + 4);
            } else {
                const uint32_t* p = (const uint32_t*)Av + (size_t)(m0 + arow) * (K / 2) + (k0 + acb) / 2;
                uint4 w = *(const uint4*)p;
                float2 f0 = unpack_bf16(w.x), f1 = unpack_bf16(w.y);
                float2 f2 = unpack_bf16(w.z), f3 = unpack_bf16(w.w);
                pa0 = make_float4(f0.x, f0.y, f1.x, f1.y);
                pa1 = make_float4(f2.x, f2.y, f3.x, f3.y);
            }
        }
        const float* q = B + (size_t)(k0 + brow) * Ncol + n0 + bcb;
        pb0 = *(const float4*)q;
        if (BN == 128) pb1 = *(const float4*)(q + 4);
    };
    auto store_tile = [&](int buf) {
        *(uint4*)&As[buf][arow][acb]     = *reinterpret_cast<uint4*>(&pa0);
        *(uint4*)&As[buf][arow][acb + 4] = *reinterpret_cast<uint4*>(&pa1);
        *(uint4*)&Bs[buf][brow][bcb]     = *reinterpret_cast<uint4*>(&pb0);
        if (BN == 128)
            *(uint4*)&Bs[buf][brow][bcb + 4] = *reinterpret_cast<uint4*>(&pb1);
    };
    auto compute = [&](int buf) {
#pragma unroll
        for (int ks = 0; ks < 16; ks += 8) {
            uint32_t a[2][4];
#pragma unroll
            for (int mf = 0; mf < 2; mf++) {
                int rb = warp_m * 32 + mf * 16;
                a[mf][0] = As[buf][rb + g][ks + t4];
                a[mf][1] = As[buf][rb + 8 + g][ks + t4];
                a[mf][2] = As[buf][rb + g][ks + 4 + t4];
                a[mf][3] = As[buf][rb + 8 + g][ks + 4 + t4];
            }
#pragma unroll
            for (int nf = 0; nf < NF; nf++) {
                int cb = warp_n * (BN / 2) + nf * 8;
                uint32_t b0 = Bs[buf][ks + t4][cb + g];
                uint32_t b1 = Bs[buf][ks + 4 + t4][cb + g];
#pragma unroll
                for (int mf = 0; mf < 2; mf++) {
                    asm volatile(
                        "mma.sync.aligned.m16n8k8.row.col.f32.tf32.tf32.f32 "
                        "{%0,%1,%2,%3}, {%4,%5,%6,%7}, {%8,%9}, {%0,%1,%2,%3};"
                        : "+f"(acc[mf][nf][0]), "+f"(acc[mf][nf][1]),
                          "+f"(acc[mf][nf][2]), "+f"(acc[mf][nf][3])
                        : "r"(a[mf][0]), "r"(a[mf][1]), "r"(a[mf][2]), "r"(a[mf][3]),
                          "r"(b0), "r"(b1));
                }
            }
        }
    };

    load_tile(0);
    store_tile(0);
    __syncthreads();
    int cur = 0;
    for (int k0 = 0; k0 < K; k0 += 16) {
        bool more = (k0 + 16 < K);
        if (more) load_tile(k0 + 16);
        compute(cur);
        if (more) store_tile(cur ^ 1);
        __syncthreads();
        cur ^= 1;
    }

    // ---- bf16 store ----
#pragma unroll
    for (int mf = 0; mf < 2; mf++) {
#pragma unroll
        for (int nf = 0; nf < NF; nf++) {
            int row0 = m0 + warp_m * 32 + mf * 16 + g;
            int col  = n0 + warp_n * (BN / 2) + nf * 8 + 2 * t4;
            if (row0 < M)
                Cb[(size_t)row0 * (Ncol / 2) + col / 2] = pack_bf16(acc[mf][nf][0], acc[mf][nf][1]);
            if (row0 + 8 < M)
                Cb[(size_t)(row0 + 8) * (Ncol / 2) + col / 2] = pack_bf16(acc[mf][nf][2], acc[mf][nf][3]);
        }
    }

    // ---- fused attention logits ----
    float2 wS[NF], wD[NF];
    int cbase = (LAYER == 1) ? ((blockIdx.x * 2 + warp_n) * 64) : (warp_n * (BN / 2));
#pragma unroll
    for (int nf = 0; nf < NF; nf++) {
        int c = cbase + nf * 8 + 2 * t4;
        wS[nf] = *(const float2*)(avS + c);
        wD[nf] = *(const float2*)(avD + c);
    }
#pragma unroll
    for (int mf = 0; mf < 2; mf++) {
        float ss0 = 0.f, dd0 = 0.f, ss1 = 0.f, dd1 = 0.f;
#pragma unroll
        for (int nf = 0; nf < NF; nf++) {
            ss0 += acc[mf][nf][0] * wS[nf].x + acc[mf][nf][1] * wS[nf].y;
            dd0 += acc[mf][nf][0] * wD[nf].x + acc[mf][nf][1] * wD[nf].y;
            ss1 += acc[mf][nf][2] * wS[nf].x + acc[mf][nf][3] * wS[nf].y;
            dd1 += acc[mf][nf][2] * wD[nf].x + acc[mf][nf][3] * wD[nf].y;
        }
        ss0 += __shfl_xor_sync(0xffffffffu, ss0, 1); ss0 += __shfl_xor_sync(0xffffffffu, ss0, 2);
        dd0 += __shfl_xor_sync(0xffffffffu, dd0, 1); dd0 += __shfl_xor_sync(0xffffffffu, dd0, 2);
        ss1 += __shfl_xor_sync(0xffffffffu, ss1, 1); ss1 += __shfl_xor_sync(0xffffffffu, ss1, 2);
        dd1 += __shfl_xor_sync(0xffffffffu, dd1, 1); dd1 += __shfl_xor_sync(0xffffffffu, dd1, 2);
        if (t4 == 0) {
            int row0 = m0 + warp_m * 32 + mf * 16 + g;
            if (LAYER == 1) {
                int head = blockIdx.x * 2 + warp_n;
                if (row0 < M)     { g_als1[row0 * 4 + head] = ss0; g_ald1[row0 * 4 + head] = dd0; }
                if (row0 + 8 < M) { g_als1[(row0 + 8) * 4 + head] = ss1; g_ald1[(row0 + 8) * 4 + head] = dd1; }
            } else {
                if (row0 < M)     { atomicAdd(&g_als2[row0], ss0); atomicAdd(&g_ald2[row0], dd0); }
                if (row0 + 8 < M) { atomicAdd(&g_als2[row0 + 8], ss1); atomicAdd(&g_ald2[row0 + 8], dd1); }
            }
        }
    }
}

__global__ void __launch_bounds__(256, 2)
gemm1_kernel(const float* __restrict__ x, const float* __restrict__ W1,
             const float* __restrict__ as1, const float* __restrict__ ad1) {
    gemm_tf32_body<128, FIN, 1>(x, W1, g_h1b, as1, ad1, NN, C1);
}
__global__ void __launch_bounds__(256, 2)
gemm2_kernel(const float* __restrict__ W2,
             const float* __restrict__ as2, const float* __restrict__ ad2) {
    gemm_tf32_body<64, C1, 2>(g_out1b, W2, g_h2b, as2, ad2, NN, HIDD);
}

// ---- layer-1 aggregation: warp per node (R10 known-good form), bf16 output ----
__global__ void agg1_kernel(const float* __restrict__ b1) {
    int n = (blockIdx.x * blockDim.x + threadIdx.x) >> 5;
    int lane = threadIdx.x & 31;
    if (n >= NN) return;
    int beg = g_row[n], end = g_row[n + 1];
    int h = lane >> 3;
    float ald = g_ald1[n * 4 + h];
    float ce  = g_scal[1 + h];
    float4 acc0 = make_float4(0.f, 0.f, 0.f, 0.f);
    float4 acc1 = make_float4(0.f, 0.f, 0.f, 0.f);
    float den = 0.f;
    int j = beg;
    for (; j + 4 <= end; j += 4) {
        int2 se[4];
#pragma unroll
        for (int q = 0; q < 4; q++) se[q] = g_elist[j + q];
        uint4 p[4]; float al[4];
#pragma unroll
        for (int q = 0; q < 4; q++) {
            p[q]  = ((const uint4*)(g_h1b + (size_t)se[q].x * (C1 / 2)))[lane];
            al[q] = g_als1[se[q].x * 4 + h];
        }
        float ex[4];
#pragma unroll
        for (int q = 0; q < 4; q++) {
            float z = al[q] + ald + __int_as_float(se[q].y) * ce;
            z = z > 0.f ? z : 0.2f * z;
            ex[q] = __expf(z);
        }
#pragma unroll
        for (int q = 0; q < 4; q++) {
            float2 f0 = unpack_bf16(p[q].x), f1 = unpack_bf16(p[q].y);
            float2 f2 = unpack_bf16(p[q].z), f3 = unpack_bf16(p[q].w);
            den += ex[q];
            acc0.x += ex[q] * f0.x; acc0.y += ex[q] * f0.y;
            acc0.z += ex[q] * f1.x; acc0.w += ex[q] * f1.y;
            acc1.x += ex[q] * f2.x; acc1.y += ex[q] * f2.y;
            acc1.z += ex[q] * f3.x; acc1.w += ex[q] * f3.y;
        }
    }
    for (; j < end; j++) {
        int2 se = g_elist[j];
        uint4 p = ((const uint4*)(g_h1b + (size_t)se.x * (C1 / 2)))[lane];
        float z = g_als1[se.x * 4 + h] + ald + __int_as_float(se.y) * ce;
        z = z > 0.f ? z : 0.2f * z;
        float ex = __expf(z);
        float2 f0 = unpack_bf16(p.x), f1 = unpack_bf16(p.y);
        float2 f2 = unpack_bf16(p.z), f3 = unpack_bf16(p.w);
        den += ex;
        acc0.x += ex * f0.x; acc0.y += ex * f0.y;
        acc0.z += ex * f1.x; acc0.w += ex * f1.y;
        acc1.x += ex * f2.x; acc1.y += ex * f2.y;
        acc1.z += ex * f3.x; acc1.w += ex * f3.y;
    }
    float inv = 1.f / (den + 1e-16f);
    const float4* bp = (const float4*)b1;
    float4 bb0 = bp[lane * 2], bb1 = bp[lane * 2 + 1];
    float o0 = fmaxf(acc0.x * inv + bb0.x, 0.f);
    float o1 = fmaxf(acc0.y * inv + bb0.y, 0.f);
    float o2 = fmaxf(acc0.z * inv + bb0.z, 0.f);
    float o3 = fmaxf(acc0.w * inv + bb0.w, 0.f);
    float o4 = fmaxf(acc1.x * inv + bb1.x, 0.f);
    float o5 = fmaxf(acc1.y * inv + bb1.y, 0.f);
    float o6 = fmaxf(acc1.z * inv + bb1.z, 0.f);
    float o7 = fmaxf(acc1.w * inv + bb1.w, 0.f);
    uint4 w;
    w.x = pack_bf16(o0, o1);
    w.y = pack_bf16(o2, o3);
    w.z = pack_bf16(o4, o5);
    w.w = pack_bf16(o6, o7);
    ((uint4*)(g_out1b + (size_t)n * (C1 / 2)))[lane] = w;
}

// ---- layer-2 aggregation (R10 known-good form) + bias + LayerNorm + pool ----
__global__ void agg2_ln_pool_kernel(const float* __restrict__ b2,
                                    const float* __restrict__ lng,
                                    const float* __restrict__ lnb,
                                    const int* __restrict__ batch) {
    int n = (blockIdx.x * blockDim.x + threadIdx.x) >> 5;
    int lane = threadIdx.x & 31;
    if (n >= NN) return;
    int beg = g_row[n], end = g_row[n + 1];
    float ald = g_ald2[n];
    float ce  = g_scal[5];
    float2 acc = make_float2(0.f, 0.f);
    float den = 0.f;
    int j = beg;
    for (; j + 4 <= end; j += 4) {
        int2 se[4];
#pragma unroll
        for (int q = 0; q < 4; q++) se[q] = g_elist[j + q];
        uint32_t p[4]; float al[4];
#pragma unroll
        for (int q = 0; q < 4; q++) {
            p[q]  = (g_h2b + (size_t)se[q].x * (HIDD / 2))[lane];
            al[q] = g_als2[se[q].x];
        }
        float ex[4];
#pragma unroll
        for (int q = 0; q < 4; q++) {
            float z = al[q] + ald + __int_as_float(se[q].y) * ce;
            z = z > 0.f ? z : 0.2f * z;
            ex[q] = __expf(z);
        }
#pragma unroll
        for (int q = 0; q < 4; q++) {
            float2 f = unpack_bf16(p[q]);
            den += ex[q];
            acc.x += ex[q] * f.x;
            acc.y += ex[q] * f.y;
        }
    }
    for (; j < end; j++) {
        int2 se = g_elist[j];
        uint32_t p = (g_h2b + (size_t)se.x * (HIDD / 2))[lane];
        float z = g_als2[se.x] + ald + __int_as_float(se.y) * ce;
        z = z > 0.f ? z : 0.2f * z;
        float ex = __expf(z);
        float2 f = unpack_bf16(p);
        den += ex;
        acc.x += ex * f.x;
        acc.y += ex * f.y;
    }
    float inv = 1.f / (den + 1e-16f);
    float2 bb = ((const float2*)b2)[lane];
    float vx = acc.x * inv + bb.x;
    float vy = acc.y * inv + bb.y;
    float s = vx + vy;
    for (int o = 16; o; o >>= 1) s += __shfl_xor_sync(0xffffffffu, s, o);
    float mu = s * (1.0f / 64.0f);
    float dx = vx - mu, dy = vy - mu;
    float q = dx * dx + dy * dy;
    for (int o = 16; o; o >>= 1) q += __shfl_xor_sync(0xffffffffu, q, o);
    float r = rsqrtf(q * (1.0f / 64.0f) + 1e-5f);
    float y0 = dx * r * lng[lane * 2]     + lnb[lane * 2];
    float y1 = dy * r * lng[lane * 2 + 1] + lnb[lane * 2 + 1];
    int g = batch[n];
    atomicAdd(&g_sums[g * 64 + lane * 2],     y0);
    atomicAdd(&g_sums[g * 64 + lane * 2 + 1], y1);
    if (lane == 0) atomicAdd(&g_cnt[g], 1.0f);
}

// ---------------- per-graph MLP head (block per graph, 64 threads) ----------------
__global__ void mlp_kernel(const float* __restrict__ clin, const float* __restrict__ met,
                           const float* __restrict__ Wf1, const float* __restrict__ bf1,
                           const float* __restrict__ Wf2, const float* __restrict__ bf2,
                           const float* __restrict__ Wr,  const float* __restrict__ br,
                           float* __restrict__ out) {
    int g = blockIdx.x, t = threadIdx.x;   // 64 threads
    __shared__ float fused[FUSED_IN];
    __shared__ float l1[64];
    __shared__ float l2[32];
    float cnt = g_cnt[g]; cnt = cnt > 1.f ? cnt : 1.f;
    float e = g_sums[g * 64 + t] / cnt;
    fused[t] = e;
    out[GG + g * 64 + t] = e;              // graph_embedding at offset 64
    if (t < 32) fused[64 + t] = clin[g * 32 + t];
    fused[96 + t]  = met[g * 128 + t];
    fused[160 + t] = met[g * 128 + 64 + t];
    __syncthreads();
    float acc = bf1[t];
#pragma unroll 8
    for (int k = 0; k < FUSED_IN; k++) acc += fused[k] * Wf1[k * 64 + t];
    l1[t] = acc > 0.f ? acc : 0.f;
    __syncthreads();
    if (t < 32) {
        float a2 = bf2[t];
#pragma unroll 8
        for (int j = 0; j < 64; j++) a2 += l1[j] * Wf2[j * 32 + t];
        a2 = a2 > 0.f ? a2 : 0.f;
        l2[t] = a2;
        out[GG + GG * 64 + g * 32 + t] = a2;   // latent at offset 64 + 4096
    }
    __syncthreads();
    if (t == 0) {
        float r = br[0];
#pragma unroll
        for (int j = 0; j < 32; j++) r += l2[j] * Wr[j];
        out[g] = r;                        // risk at offset 0
    }
}

// ---------------- launch ----------------
extern "C" void kernel_launch(void* const* d_in, const int* in_sizes, int n_in,
                              void* d_out, int out_size) {
    const float* x    = (const float*)d_in[0];
    const int*   ei   = (const int*)d_in[1];
    const float* ea   = (const float*)d_in[2];
    const int*   bat  = (const int*)d_in[3];
    const float* clin = (const float*)d_in[4];
    const float* met  = (const float*)d_in[5];
    const float* W1   = (const float*)d_in[6];
    const float* as1  = (const float*)d_in[7];
    const float* ad1  = (const float*)d_in[8];
    const float* ae1  = (const float*)d_in[9];
    const float* We1  = (const float*)d_in[10];
    const float* b1   = (const float*)d_in[11];
    const float* W2   = (const float*)d_in[12];
    const float* as2  = (const float*)d_in[13];
    const float* ad2  = (const float*)d_in[14];
    const float* ae2  = (const float*)d_in[15];
    const float* We2  = (const float*)d_in[16];
    const float* b2   = (const float*)d_in[17];
    const float* lng  = (const float*)d_in[18];
    const float* lnb  = (const float*)d_in[19];
    const float* Wf1  = (const float*)d_in[20];
    const float* bf1  = (const float*)d_in[21];
    const float* Wf2  = (const float*)d_in[22];
    const float* bf2  = (const float*)d_in[23];
    const float* Wr   = (const float*)d_in[24];
    const float* br   = (const float*)d_in[25];
    float* out = (float*)d_out;

    // fork: CSR chain on side stream, GEMM(+logits) on main stream
    cudaStream_t s2;
    cudaEvent_t e0, e1;
    cudaStreamCreateWithFlags(&s2, cudaStreamNonBlocking);
    cudaEventCreateWithFlags(&e0, cudaEventDisableTiming);
    cudaEventCreateWithFlags(&e1, cudaEventDisableTiming);

    cudaEventRecord(e0, 0);
    cudaStreamWaitEvent(s2, e0, 0);

    prep_kernel<<<512, 256, 0, s2>>>(ea);                        // 0
    hist_kernel<<<(ELOOP + 255) / 256, 256, 0, s2>>>(ei);        // 1
    scan1_kernel<<<NB, 256, 0, s2>>>();                          // 2
    gemm1_kernel<<<dim3(C1 / 128, (NN + 127) / 128), 256>>>(x, W1, as1, ad1); // 3 (profiled)
    scan2_kernel<<<1, 256, 0, s2>>>(We1, ae1, We2, ae2);         // 4
    scan3_kernel<<<NB, 256, 0, s2>>>();                          // 5
    scatter_kernel<<<(ELOOP + 255) / 256, 256, 0, s2>>>(ei, ea); // 6
    cudaEventRecord(e1, s2);
    cudaStreamWaitEvent(0, e1, 0);

    // layer 1 aggregation (needs CSR + gemm1 logits): 1 warp/node (R10 form)
    agg1_kernel<<<(NN * 32 + 255) / 256, 256>>>(b1);

    // layer 2 (gemm2 fuses logits2, reads bf16 out1; g_als2/g_ald2 zeroed by prep)
    gemm2_kernel<<<dim3(1, (NN + 127) / 128), 256>>>(W2, as2, ad2);
    agg2_ln_pool_kernel<<<(NN * 32 + 255) / 256, 256>>>(b2, lng, lnb, bat);

    // head
    mlp_kernel<<<GG, 64>>>(clin, met, Wf1, bf1, Wf2, bf2, Wr, br, out);
    // streams/events intentionally not destroyed (graph may reference them)
}